// round 2
// baseline (speedup 1.0000x reference)
#include <cuda_runtime.h>
#include <math.h>

#define NN 50000
#define EE 800000
#define FIN 256
#define HID 128
#define NCLS 40

// ---------------- scratch (device globals; no allocation allowed) ----------------
__device__ int   g_is64;
__device__ int   g_src[EE];
__device__ int   g_dst[EE];
__device__ int   g_deg[NN];
__device__ float g_dinv[NN];
__device__ int   g_off[NN + 1];
__device__ int   g_cursor[NN];
__device__ __align__(16) int2  g_csrw[EE];                 // (src, dinv[src] bits)
__device__ __align__(16) float g_Wc1[FIN * 3 * HID];       // 256x384
__device__ __align__(16) float g_Wc2[3 * HID * 3 * NCLS];  // 384x120
__device__ __align__(16) float g_G[(size_t)NN * 3 * HID];  // 50000x384
__device__ __align__(16) float g_U[(size_t)NN * 2 * HID];  // 50000x256
__device__ __align__(16) float g_V[(size_t)NN * HID];      // 50000x128
__device__ __align__(16) float g_h[(size_t)NN * 3 * HID];  // 50000x384
__device__ __align__(16) float g_Fb[(size_t)NN * 3 * NCLS];  // 50000x120
__device__ __align__(16) float g_Rb[(size_t)NN * 2 * NCLS];  // 50000x80
__device__ __align__(16) float g_Sb[(size_t)NN * NCLS];      // 50000x40

// ---------------- dtype detection + normalization ----------------
// If the buffer is int64 (values < 2^31), every high 32-bit word is 0.
// If int32, odd words are node indices (nonzero with prob ~1-2e-5 each).
__global__ void k_detect(const int2* __restrict__ ei2, int e) {
    __shared__ int nonzero;
    if (threadIdx.x == 0) nonzero = 0;
    __syncthreads();
    int t = threadIdx.x;
    if (t < 256 && t < e) {
        int2 p = ei2[t];
        if (p.y != 0) atomicAdd(&nonzero, 1);
    }
    __syncthreads();
    if (threadIdx.x == 0) g_is64 = (nonzero == 0) ? 1 : 0;
}

__global__ void k_convert(const void* __restrict__ ei, int e) {
    int t = blockIdx.x * blockDim.x + threadIdx.x;
    if (t >= e) return;
    int s, d;
    if (g_is64) {
        const long long* p = (const long long*)ei;
        s = (int)p[t];
        d = (int)p[(size_t)e + t];
    } else {
        const int* p = (const int*)ei;
        s = p[t];
        d = p[e + t];
    }
    g_src[t] = s;
    g_dst[t] = d;
}

// ---------------- preprocessing ----------------
__global__ void k_init(int n) {
    int i = blockIdx.x * blockDim.x + threadIdx.x;
    if (i < n) g_deg[i] = 1;  // self loop
}

__global__ void k_deg(int e) {
    int t = blockIdx.x * blockDim.x + threadIdx.x;
    if (t < e) atomicAdd(&g_deg[g_dst[t]], 1);
}

__global__ void k_dinv(int n) {
    int i = blockIdx.x * blockDim.x + threadIdx.x;
    if (i < n) g_dinv[i] = rsqrtf((float)g_deg[i]);
}

// single-block exclusive scan of (deg-1); also fills cursor and off[n]=E
__global__ __launch_bounds__(1024) void k_scan(int n, int e_total) {
    __shared__ int wsum[32];
    int tid = threadIdx.x;
    int lane = tid & 31, wid = tid >> 5;
    int chunk = (n + 1023) / 1024;
    int b = tid * chunk;
    int en = b + chunk; if (en > n) en = n;
    int s = 0;
    for (int i = b; i < en; i++) s += g_deg[i] - 1;
    int v = s;
    #pragma unroll
    for (int o = 1; o < 32; o <<= 1) {
        int t = __shfl_up_sync(0xffffffffu, v, o);
        if (lane >= o) v += t;
    }
    if (lane == 31) wsum[wid] = v;
    __syncthreads();
    if (wid == 0) {
        int w = wsum[lane];
        #pragma unroll
        for (int o = 1; o < 32; o <<= 1) {
            int t = __shfl_up_sync(0xffffffffu, w, o);
            if (lane >= o) w += t;
        }
        wsum[lane] = w;
    }
    __syncthreads();
    int run = (v - s) + (wid ? wsum[wid - 1] : 0);
    for (int i = b; i < en; i++) {
        g_off[i] = run;
        g_cursor[i] = run;
        run += g_deg[i] - 1;
    }
    if (tid == 0) g_off[n] = e_total;
}

__global__ void k_scatter(int e) {
    int t = blockIdx.x * blockDim.x + threadIdx.x;
    if (t < e) {
        int s = g_src[t];
        int d = g_dst[t];
        int p = atomicAdd(&g_cursor[d], 1);
        g_csrw[p] = make_int2(s, __float_as_int(g_dinv[s]));
    }
}

__global__ void k_cat1(const float* __restrict__ w0, const float* __restrict__ w1,
                       const float* __restrict__ w2) {
    int g = blockIdx.x * blockDim.x + threadIdx.x;
    if (g >= 3 * FIN * HID) return;
    int p = g / (FIN * HID);
    int r = g % (FIN * HID);
    int k = r / HID, nn = r % HID;
    const float* w = (p == 0) ? w0 : (p == 1) ? w1 : w2;
    g_Wc1[k * (3 * HID) + p * HID + nn] = w[r];
}

__global__ void k_cat2(const float* __restrict__ w0, const float* __restrict__ w1,
                       const float* __restrict__ w2) {
    int g = blockIdx.x * blockDim.x + threadIdx.x;
    if (g >= 3 * 3 * HID * NCLS) return;
    int p = g / (3 * HID * NCLS);
    int r = g % (3 * HID * NCLS);
    int k = r / NCLS, nn = r % NCLS;
    const float* w = (p == 0) ? w0 : (p == 1) ? w1 : w2;
    g_Wc2[k * (3 * NCLS) + p * NCLS + nn] = w[r];
}

// ---------------- SGEMM 128x(Ncols)x8, 8x8 per thread ----------------
// LAYER 1: A=x (param), B=g_Wc1, C=g_G,  N=384, K=256
// LAYER 2: A=g_h,       B=g_Wc2, C=g_Fb, N=120, K=384
template <int LAYER>
__global__ __launch_bounds__(256) void k_sgemm(const float* __restrict__ x, int M) {
    const float* __restrict__ A = (LAYER == 1) ? x : g_h;
    const float* __restrict__ B = (LAYER == 1) ? g_Wc1 : g_Wc2;
    float* __restrict__ C = (LAYER == 1) ? g_G : g_Fb;
    constexpr int N = (LAYER == 1) ? 3 * HID : 3 * NCLS;
    constexpr int K = (LAYER == 1) ? FIN : 3 * HID;

    __shared__ float As[8][128];
    __shared__ float Bs[8][128];
    int tid = threadIdx.x;
    int bm = blockIdx.y * 128;
    int bn = blockIdx.x * 128;
    int aRow = tid >> 1;
    int aCol = (tid & 1) << 2;
    int bRow = tid >> 5;
    int bCol = (tid & 31) << 2;
    int tx = tid & 15, ty = tid >> 4;

    float acc[8][8];
    #pragma unroll
    for (int i = 0; i < 8; i++)
        #pragma unroll
        for (int j = 0; j < 8; j++) acc[i][j] = 0.0f;

    bool aValid = (bm + aRow) < M;
    const float* Ap = A + (size_t)(bm + aRow) * K + aCol;
    bool bValid = (bn + bCol) < N;

    for (int k0 = 0; k0 < K; k0 += 8) {
        float4 av = aValid ? *(const float4*)(Ap + k0) : make_float4(0, 0, 0, 0);
        float4 bv = bValid ? *(const float4*)(B + (size_t)(k0 + bRow) * N + bn + bCol)
                           : make_float4(0, 0, 0, 0);
        As[aCol + 0][aRow] = av.x;
        As[aCol + 1][aRow] = av.y;
        As[aCol + 2][aRow] = av.z;
        As[aCol + 3][aRow] = av.w;
        *(float4*)&Bs[bRow][bCol] = bv;
        __syncthreads();
        #pragma unroll
        for (int k = 0; k < 8; k++) {
            float ar[8], br[8];
            #pragma unroll
            for (int i = 0; i < 8; i++) ar[i] = As[k][ty * 8 + i];
            #pragma unroll
            for (int j = 0; j < 8; j++) br[j] = Bs[k][tx * 8 + j];
            #pragma unroll
            for (int i = 0; i < 8; i++)
                #pragma unroll
                for (int j = 0; j < 8; j++) acc[i][j] += ar[i] * br[j];
        }
        __syncthreads();
    }

    #pragma unroll
    for (int i = 0; i < 8; i++) {
        int r = bm + ty * 8 + i;
        if (r >= M) continue;
        #pragma unroll
        for (int j = 0; j < 8; j += 4) {
            int c = bn + tx * 8 + j;
            if (c < N)
                *(float4*)&C[(size_t)r * N + c] =
                    make_float4(acc[i][j], acc[i][j + 1], acc[i][j + 2], acc[i][j + 3]);
        }
    }
}

// ---------------- SpMM: one warp per row, CSR, register accumulate ----------------
// WHICH 0: g_G[:,128:384] (stride 384) -> g_U (256 cols)
// WHICH 1: g_U[:,128:256] (stride 256) -> g_V (128 cols)
// WHICH 2: g_Fb[:,40:120] (stride 120) -> g_Rb (80 cols)
// WHICH 3: g_Rb[:,40:80]  (stride 80)  -> g_Sb (40 cols)
template <int NV4, int WHICH>
__global__ __launch_bounds__(256) void k_spmm(int n) {
    const float* __restrict__ in =
        (WHICH == 0) ? (g_G + 128) : (WHICH == 1) ? (g_U + 128)
        : (WHICH == 2) ? (g_Fb + NCLS) : (g_Rb + NCLS);
    float* __restrict__ out =
        (WHICH == 0) ? g_U : (WHICH == 1) ? g_V : (WHICH == 2) ? g_Rb : g_Sb;
    constexpr int istride = (WHICH == 0) ? 3 * HID : (WHICH == 1) ? 2 * HID
                            : (WHICH == 2) ? 3 * NCLS : 2 * NCLS;
    constexpr int ostride = (WHICH == 0) ? 2 * HID : (WHICH == 1) ? HID
                            : (WHICH == 2) ? 2 * NCLS : NCLS;

    int w = (blockIdx.x * blockDim.x + threadIdx.x) >> 5;
    int lane = threadIdx.x & 31;
    if (w >= n) return;
    float di = g_dinv[w];
    constexpr int IT = (NV4 + 31) / 32;
    float4 acc[IT];
    const float4* xr = (const float4*)(in + (size_t)w * istride);
    #pragma unroll
    for (int t = 0; t < IT; t++) {
        int c = lane + 32 * t;
        if ((NV4 % 32 == 0) || c < NV4) {
            float4 v = xr[c];
            acc[t] = make_float4(di * v.x, di * v.y, di * v.z, di * v.w);
        } else {
            acc[t] = make_float4(0, 0, 0, 0);
        }
    }
    int jb = g_off[w], je = g_off[w + 1];
    int2 nxt = make_int2(0, 0);
    if (jb < je) nxt = g_csrw[jb];
    for (int j = jb; j < je; j++) {
        int2 cur = nxt;
        if (j + 1 < je) nxt = g_csrw[j + 1];
        int s = cur.x;
        float ws = __int_as_float(cur.y);
        const float4* xs = (const float4*)(in + (size_t)s * istride);
        #pragma unroll
        for (int t = 0; t < IT; t++) {
            int c = lane + 32 * t;
            if ((NV4 % 32 == 0) || c < NV4) {
                float4 v = __ldg(&xs[c]);
                acc[t].x += ws * v.x;
                acc[t].y += ws * v.y;
                acc[t].z += ws * v.z;
                acc[t].w += ws * v.w;
            }
        }
    }
    float4* o = (float4*)(out + (size_t)w * ostride);
    #pragma unroll
    for (int t = 0; t < IT; t++) {
        int c = lane + 32 * t;
        if ((NV4 % 32 == 0) || c < NV4)
            o[c] = make_float4(di * acc[t].x, di * acc[t].y, di * acc[t].z, di * acc[t].w);
    }
}

// ---------------- build h = relu(concat + b1) ----------------
__global__ void k_buildh(const float* __restrict__ b1, int n) {
    int g = blockIdx.x * blockDim.x + threadIdx.x;
    if (g >= n * 96) return;
    int i = g / 96, c4 = g % 96;
    float4 v;
    if (c4 < 32)
        v = ((const float4*)g_G)[(size_t)i * 96 + c4];
    else if (c4 < 64)
        v = ((const float4*)g_U)[(size_t)i * 64 + (c4 - 32)];
    else
        v = ((const float4*)g_V)[(size_t)i * 32 + (c4 - 64)];
    float4 bb = ((const float4*)b1)[c4];
    v.x = fmaxf(v.x + bb.x, 0.0f);
    v.y = fmaxf(v.y + bb.y, 0.0f);
    v.z = fmaxf(v.z + bb.z, 0.0f);
    v.w = fmaxf(v.w + bb.w, 0.0f);
    ((float4*)g_h)[(size_t)i * 96 + c4] = v;
}

// ---------------- final: gather blocks + b2, log_softmax over 120 ----------------
__global__ __launch_bounds__(256) void k_lsm(const float* __restrict__ b2,
                                             float* __restrict__ out, int n) {
    int w = (blockIdx.x * blockDim.x + threadIdx.x) >> 5;
    int lane = threadIdx.x & 31;
    if (w >= n) return;
    float4 v = make_float4(0, 0, 0, 0);
    bool act = lane < 30;
    if (act) {
        if (lane < 10)
            v = ((const float4*)g_Fb)[(size_t)w * 30 + lane];
        else if (lane < 20)
            v = ((const float4*)g_Rb)[(size_t)w * 20 + (lane - 10)];
        else
            v = ((const float4*)g_Sb)[(size_t)w * 10 + (lane - 20)];
        float4 bb = ((const float4*)b2)[lane];
        v.x += bb.x; v.y += bb.y; v.z += bb.z; v.w += bb.w;
    }
    float m = act ? fmaxf(fmaxf(v.x, v.y), fmaxf(v.z, v.w)) : -INFINITY;
    #pragma unroll
    for (int o = 16; o > 0; o >>= 1) m = fmaxf(m, __shfl_xor_sync(0xffffffffu, m, o));
    float s = 0.0f;
    if (act) s = expf(v.x - m) + expf(v.y - m) + expf(v.z - m) + expf(v.w - m);
    #pragma unroll
    for (int o = 16; o > 0; o >>= 1) s += __shfl_xor_sync(0xffffffffu, s, o);
    float lse = m + logf(s);
    if (act) {
        float4 r = make_float4(v.x - lse, v.y - lse, v.z - lse, v.w - lse);
        ((float4*)out)[(size_t)w * 30 + lane] = r;
    }
}

// ---------------- launch ----------------
extern "C" void kernel_launch(void* const* d_in, const int* in_sizes, int n_in,
                              void* d_out, int out_size) {
    const float* x = (const float*)d_in[0];
    const void* ei = d_in[1];
    const float* W1_0 = (const float*)d_in[2];
    const float* W1_1 = (const float*)d_in[3];
    const float* W1_2 = (const float*)d_in[4];
    const float* b1 = (const float*)d_in[5];
    const float* W2_0 = (const float*)d_in[6];
    const float* W2_1 = (const float*)d_in[7];
    const float* W2_2 = (const float*)d_in[8];
    const float* b2 = (const float*)d_in[9];
    float* out = (float*)d_out;

    int n = in_sizes[0] / FIN;  // 50000
    int e = in_sizes[1] / 2;    // 800000 (element count is 2E for either dtype)

    // preprocessing
    k_detect<<<1, 256>>>((const int2*)ei, e);
    k_convert<<<(e + 255) / 256, 256>>>(ei, e);
    k_init<<<(n + 255) / 256, 256>>>(n);
    k_deg<<<(e + 255) / 256, 256>>>(e);
    k_dinv<<<(n + 255) / 256, 256>>>(n);
    k_scan<<<1, 1024>>>(n, e);
    k_scatter<<<(e + 255) / 256, 256>>>(e);
    k_cat1<<<(3 * FIN * HID + 255) / 256, 256>>>(W1_0, W1_1, W1_2);
    k_cat2<<<(3 * 3 * HID * NCLS + 255) / 256, 256>>>(W2_0, W2_1, W2_2);

    // layer 1: G = x @ [W0|W1|W2]   (50000x384)
    {
        dim3 grid((3 * HID + 127) / 128, (n + 127) / 128);
        k_sgemm<1><<<grid, 256>>>(x, n);
    }
    {
        int blocks = (n + 7) / 8;
        k_spmm<64, 0><<<blocks, 256>>>(n);  // U = P(G[:,128:384])
        k_spmm<32, 1><<<blocks, 256>>>(n);  // V = P(U[:,128:256])
    }
    k_buildh<<<(n * 96 + 255) / 256, 256>>>(b1, n);

    // layer 2: F = h @ [W0|W1|W2]   (50000x120)
    {
        dim3 grid((3 * NCLS + 127) / 128, (n + 127) / 128);
        k_sgemm<2><<<grid, 256>>>(x /*unused*/, n);
    }
    {
        int blocks = (n + 7) / 8;
        k_spmm<20, 2><<<blocks, 256>>>(n);  // R = P(F[:,40:120])
        k_spmm<10, 3><<<blocks, 256>>>(n);  // S = P(R[:,40:80])
    }
    k_lsm<<<(n + 7) / 8, 256>>>(b2, out, n);
}

// round 4
// speedup vs baseline: 1.3254x; 1.3254x over previous
#include <cuda_runtime.h>
#include <cuda_bf16.h>
#include <math.h>
#include <stdint.h>

#define NN 50000
#define EE 800000
#define FIN 256
#define HID 128
#define NCLS 40

// ---------------- scratch (device globals; no allocation allowed) ----------------
__device__ int   g_is64;
__device__ int   g_src[EE];
__device__ int   g_dst[EE];
__device__ int   g_deg[NN];
__device__ float g_dinv[NN];
__device__ int   g_off[NN + 1];
__device__ int   g_cursor[NN];
__device__ __align__(16) int2  g_csrw[EE];  // (src, dinv[src] bits)

__device__ __align__(16) __nv_bfloat16 g_xhi[(size_t)NN * FIN];
__device__ __align__(16) __nv_bfloat16 g_xlo[(size_t)NN * FIN];
__device__ __align__(16) __nv_bfloat16 g_w1t_hi[384 * 256];   // [N=384][K=256]
__device__ __align__(16) __nv_bfloat16 g_w1t_lo[384 * 256];
__device__ __align__(16) __nv_bfloat16 g_w2t_hi[120 * 384];   // [N=120][K=384]
__device__ __align__(16) __nv_bfloat16 g_w2t_lo[120 * 384];
__device__ __align__(16) __nv_bfloat16 g_hhi[(size_t)NN * 384];
__device__ __align__(16) __nv_bfloat16 g_hlo[(size_t)NN * 384];

__device__ __align__(16) float g_G[(size_t)NN * 256];   // x@[W1|W2] (SpMM input)
__device__ __align__(16) float g_U[(size_t)NN * 256];   // P(G)
__device__ __align__(16) float g_V[(size_t)NN * 128];   // P(U[:,128:256])
__device__ __align__(16) float g_Fb[(size_t)NN * 120];  // h@[W0|W1|W2]
__device__ __align__(16) float g_Rb[(size_t)NN * 80];
__device__ __align__(16) float g_Sb[(size_t)NN * 40];

// ---------------- helpers ----------------
__device__ __forceinline__ uint32_t smem_u32(const void* p) {
    uint32_t a;
    asm("{ .reg .u64 t; cvta.to.shared.u64 t, %1; cvt.u32.u64 %0, t; }" : "=r"(a) : "l"(p));
    return a;
}

__device__ __forceinline__ void ldm_x4(uint32_t* r, uint32_t addr) {
    asm volatile("ldmatrix.sync.aligned.m8n8.x4.shared.b16 {%0,%1,%2,%3}, [%4];"
                 : "=r"(r[0]), "=r"(r[1]), "=r"(r[2]), "=r"(r[3]) : "r"(addr));
}

__device__ __forceinline__ void mma_bf16(float* d, const uint32_t* a, uint32_t b0, uint32_t b1) {
    asm volatile(
        "mma.sync.aligned.m16n8k16.row.col.f32.bf16.bf16.f32 "
        "{%0,%1,%2,%3}, {%4,%5,%6,%7}, {%8,%9}, {%0,%1,%2,%3};"
        : "+f"(d[0]), "+f"(d[1]), "+f"(d[2]), "+f"(d[3])
        : "r"(a[0]), "r"(a[1]), "r"(a[2]), "r"(a[3]), "r"(b0), "r"(b1));
}

__device__ __forceinline__ void bf16split(float a, __nv_bfloat16& h, __nv_bfloat16& l) {
    h = __float2bfloat16_rn(a);
    l = __float2bfloat16_rn(a - __bfloat162float(h));
}

// ---------------- dtype detection + normalization ----------------
__global__ void k_detect(const int2* __restrict__ ei2, int e) {
    __shared__ int nonzero;
    if (threadIdx.x == 0) nonzero = 0;
    __syncthreads();
    int t = threadIdx.x;
    if (t < 256 && t < e) {
        int2 p = ei2[t];
        if (p.y != 0) atomicAdd(&nonzero, 1);
    }
    __syncthreads();
    if (threadIdx.x == 0) g_is64 = (nonzero == 0) ? 1 : 0;
}

__global__ void k_convert(const void* __restrict__ ei, int e) {
    int t = blockIdx.x * blockDim.x + threadIdx.x;
    if (t >= e) return;
    int s, d;
    if (g_is64) {
        const long long* p = (const long long*)ei;
        s = (int)p[t];
        d = (int)p[(size_t)e + t];
    } else {
        const int* p = (const int*)ei;
        s = p[t];
        d = p[e + t];
    }
    g_src[t] = s;
    g_dst[t] = d;
}

// ---------------- graph preprocessing ----------------
__global__ void k_init(int n) {
    int i = blockIdx.x * blockDim.x + threadIdx.x;
    if (i < n) g_deg[i] = 1;
}

__global__ void k_deg(int e) {
    int t = blockIdx.x * blockDim.x + threadIdx.x;
    if (t < e) atomicAdd(&g_deg[g_dst[t]], 1);
}

__global__ void k_dinv(int n) {
    int i = blockIdx.x * blockDim.x + threadIdx.x;
    if (i < n) g_dinv[i] = rsqrtf((float)g_deg[i]);
}

__global__ __launch_bounds__(1024) void k_scan(int n, int e_total) {
    __shared__ int wsum[32];
    int tid = threadIdx.x;
    int lane = tid & 31, wid = tid >> 5;
    int chunk = (n + 1023) / 1024;
    int b = tid * chunk;
    int en = b + chunk; if (en > n) en = n;
    int s = 0;
    for (int i = b; i < en; i++) s += g_deg[i] - 1;
    int v = s;
    #pragma unroll
    for (int o = 1; o < 32; o <<= 1) {
        int t = __shfl_up_sync(0xffffffffu, v, o);
        if (lane >= o) v += t;
    }
    if (lane == 31) wsum[wid] = v;
    __syncthreads();
    if (wid == 0) {
        int w = wsum[lane];
        #pragma unroll
        for (int o = 1; o < 32; o <<= 1) {
            int t = __shfl_up_sync(0xffffffffu, w, o);
            if (lane >= o) w += t;
        }
        wsum[lane] = w;
    }
    __syncthreads();
    int run = (v - s) + (wid ? wsum[wid - 1] : 0);
    for (int i = b; i < en; i++) {
        g_off[i] = run;
        g_cursor[i] = run;
        run += g_deg[i] - 1;
    }
    if (tid == 0) g_off[n] = e_total;
}

__global__ void k_scatter(int e) {
    int t = blockIdx.x * blockDim.x + threadIdx.x;
    if (t < e) {
        int s = g_src[t];
        int d = g_dst[t];
        int p = atomicAdd(&g_cursor[d], 1);
        g_csrw[p] = make_int2(s, __float_as_int(g_dinv[s]));
    }
}

// ---------------- data conversion ----------------
__global__ void k_xsplit(const float* __restrict__ x, int total4) {
    int i = blockIdx.x * blockDim.x + threadIdx.x;
    if (i >= total4) return;
    float4 v = ((const float4*)x)[i];
    __nv_bfloat16 h0, h1, h2, h3, l0, l1, l2, l3;
    bf16split(v.x, h0, l0); bf16split(v.y, h1, l1);
    bf16split(v.z, h2, l2); bf16split(v.w, h3, l3);
    ((__nv_bfloat162*)g_xhi)[i * 2] = __halves2bfloat162(h0, h1);
    ((__nv_bfloat162*)g_xhi)[i * 2 + 1] = __halves2bfloat162(h2, h3);
    ((__nv_bfloat162*)g_xlo)[i * 2] = __halves2bfloat162(l0, l1);
    ((__nv_bfloat162*)g_xlo)[i * 2 + 1] = __halves2bfloat162(l2, l3);
}

// W1T[n*256+k] = W1_{n/128}[k*128 + n%128]
__global__ void k_w1t(const float* __restrict__ w0, const float* __restrict__ w1,
                      const float* __restrict__ w2) {
    int g = blockIdx.x * blockDim.x + threadIdx.x;
    if (g >= 384 * 256) return;
    int n = g / 256, k = g % 256;
    const float* w = (n < 128) ? w0 : (n < 256) ? w1 : w2;
    float v = w[k * 128 + (n & 127)];
    __nv_bfloat16 h, l;
    bf16split(v, h, l);
    g_w1t_hi[g] = h;
    g_w1t_lo[g] = l;
}

// W2T[n*384+k] = W2_{n/40}[k*40 + n%40]
__global__ void k_w2t(const float* __restrict__ w0, const float* __restrict__ w1,
                      const float* __restrict__ w2) {
    int g = blockIdx.x * blockDim.x + threadIdx.x;
    if (g >= 120 * 384) return;
    int n = g / 384, k = g % 384;
    const float* w = (n < 40) ? w0 : (n < 80) ? w1 : w2;
    float v = w[k * 40 + (n % 40)];
    __nv_bfloat16 h, l;
    bf16split(v, h, l);
    g_w2t_hi[g] = h;
    g_w2t_lo[g] = l;
}

// ---------------- mma.sync GEMM (bf16 3-split) ----------------
// Block tile 128x128, 8 warps (4m x 2n), warp tile 32x64, K in 64-col chunks.
// Smem tiles padded to pitch 72 bf16 (144B rows -> ldmatrix conflict-free).
#define SPITCH 72
#define OFF_AH 0
#define OFF_AL (128 * SPITCH)
#define OFF_BH (2 * 128 * SPITCH)
#define OFF_BL (3 * 128 * SPITCH)
#define SMEMSZ (4 * 128 * SPITCH * 2)  // 73728 bytes

__device__ __forceinline__ void ld_tile_sm(__nv_bfloat16* dst, const __nv_bfloat16* __restrict__ src,
                                           int row0, int validRows, int pitch, int k0, int tid) {
    #pragma unroll
    for (int it = 0; it < 4; it++) {
        int slot = tid + it * 256;  // 1024 slots = 128 rows x 8 float4
        int row = slot >> 3, q = slot & 7;
        float4 v = make_float4(0.f, 0.f, 0.f, 0.f);
        if (row < validRows)
            v = *reinterpret_cast<const float4*>(src + (size_t)(row0 + row) * pitch + k0 + q * 8);
        *reinterpret_cast<float4*>(dst + row * SPITCH + q * 8) = v;
    }
}

template <int LAYER>
__global__ __launch_bounds__(256) void k_mma(const float* __restrict__ b1, int M) {
    constexpr int K = (LAYER == 1) ? 256 : 384;
    constexpr int CH = K / 64;
    constexpr int APITCH = (LAYER == 1) ? 256 : 384;
    constexpr int BROWS = (LAYER == 1) ? 128 : 120;

    extern __shared__ __align__(16) __nv_bfloat16 sm[];
    uint32_t sbase = smem_u32(sm);

    int tid = threadIdx.x;
    int warp = tid >> 5, lane = tid & 31;
    int wm = warp & 3, wn = warp >> 2;  // 4 x 2 warp grid
    int rowSel = lane & 15;
    int kSel = (lane >> 4) << 3;

    int bm = blockIdx.y * 128, bn = blockIdx.x * 128;
    int rowsA = M - bm; if (rowsA > 128) rowsA = 128;

    const __nv_bfloat16* Ah = (LAYER == 1) ? g_xhi : g_hhi;
    const __nv_bfloat16* Al = (LAYER == 1) ? g_xlo : g_hlo;
    const __nv_bfloat16* Bh = (LAYER == 1) ? g_w1t_hi : g_w2t_hi;
    const __nv_bfloat16* Bl = (LAYER == 1) ? g_w1t_lo : g_w2t_lo;

    float acc[2][8][4];
    #pragma unroll
    for (int i = 0; i < 2; i++)
        #pragma unroll
        for (int j = 0; j < 8; j++)
            #pragma unroll
            for (int q = 0; q < 4; q++) acc[i][j][q] = 0.f;

    for (int c = 0; c < CH; c++) {
        int k0 = c * 64;
        ld_tile_sm(sm + OFF_AH, Ah, bm, rowsA, APITCH, k0, tid);
        ld_tile_sm(sm + OFF_AL, Al, bm, rowsA, APITCH, k0, tid);
        ld_tile_sm(sm + OFF_BH, Bh, bn, BROWS, K, k0, tid);
        ld_tile_sm(sm + OFF_BL, Bl, bn, BROWS, K, k0, tid);
        __syncthreads();
        #pragma unroll
        for (int kb = 0; kb < 64; kb += 16) {
            uint32_t aH[2][4], aL[2][4];
            #pragma unroll
            for (int i = 0; i < 2; i++) {
                uint32_t rowA = wm * 32 + i * 16 + rowSel;
                ldm_x4(aH[i], sbase + 2u * (OFF_AH + rowA * SPITCH + kb + kSel));
                ldm_x4(aL[i], sbase + 2u * (OFF_AL + rowA * SPITCH + kb + kSel));
            }
            #pragma unroll
            for (int jj = 0; jj < 4; jj++) {
                uint32_t bH[4], bL[4];
                uint32_t rowB = wn * 64 + jj * 16 + rowSel;
                ldm_x4(bH, sbase + 2u * (OFF_BH + rowB * SPITCH + kb + kSel));
                ldm_x4(bL, sbase + 2u * (OFF_BL + rowB * SPITCH + kb + kSel));
                #pragma unroll
                for (int i = 0; i < 2; i++) {
                    mma_bf16(acc[i][2 * jj], aH[i], bH[0], bH[2]);
                    mma_bf16(acc[i][2 * jj], aL[i], bH[0], bH[2]);
                    mma_bf16(acc[i][2 * jj], aH[i], bL[0], bL[2]);
                    mma_bf16(acc[i][2 * jj + 1], aH[i], bH[1], bH[3]);
                    mma_bf16(acc[i][2 * jj + 1], aL[i], bH[1], bH[3]);
                    mma_bf16(acc[i][2 * jj + 1], aH[i], bL[1], bL[3]);
                }
            }
        }
        __syncthreads();
    }

    // epilogue — fragment (m16n8): rows g, g+8; cols tg*2, tg*2+1
    int g = lane >> 2, tg = lane & 3;
    int m0 = bm + wm * 32;
    int nb = wn * 64;  // col offset within 128-wide n tile
    #pragma unroll
    for (int i = 0; i < 2; i++) {
        int r0 = m0 + i * 16 + g;
        int r1 = r0 + 8;
        #pragma unroll
        for (int j = 0; j < 8; j++) {
            int cl = nb + j * 8 + tg * 2;  // local col in [0,128)
            float2 v0 = make_float2(acc[i][j][0], acc[i][j][1]);
            float2 v1 = make_float2(acc[i][j][2], acc[i][j][3]);
            if (LAYER == 1) {
                if (blockIdx.x == 0) {
                    // h[:,0:128] = relu(D + b1) -> bf16 hi/lo
                    float2 bb = *(const float2*)&b1[cl];
                    if (r0 < M) {
                        float a0 = fmaxf(v0.x + bb.x, 0.f), a1 = fmaxf(v0.y + bb.y, 0.f);
                        __nv_bfloat16 h0, h1, l0, l1;
                        bf16split(a0, h0, l0); bf16split(a1, h1, l1);
                        *(__nv_bfloat162*)&g_hhi[(size_t)r0 * 384 + cl] = __halves2bfloat162(h0, h1);
                        *(__nv_bfloat162*)&g_hlo[(size_t)r0 * 384 + cl] = __halves2bfloat162(l0, l1);
                    }
                    if (r1 < M) {
                        float a0 = fmaxf(v1.x + bb.x, 0.f), a1 = fmaxf(v1.y + bb.y, 0.f);
                        __nv_bfloat16 h0, h1, l0, l1;
                        bf16split(a0, h0, l0); bf16split(a1, h1, l1);
                        *(__nv_bfloat162*)&g_hhi[(size_t)r1 * 384 + cl] = __halves2bfloat162(h0, h1);
                        *(__nv_bfloat162*)&g_hlo[(size_t)r1 * 384 + cl] = __halves2bfloat162(l0, l1);
                    }
                } else {
                    int cg = (blockIdx.x - 1) * 128 + cl;  // col in G [0,256)
                    if (r0 < M) *(float2*)&g_G[(size_t)r0 * 256 + cg] = v0;
                    if (r1 < M) *(float2*)&g_G[(size_t)r1 * 256 + cg] = v1;
                }
            } else {
                if (cl < 120) {
                    if (r0 < M) *(float2*)&g_Fb[(size_t)r0 * 120 + cl] = v0;
                    if (r1 < M) *(float2*)&g_Fb[(size_t)r1 * 120 + cl] = v1;
                }
            }
        }
    }
}

// ---------------- SpMM: one warp per row, CSR, register accumulate ----------------
// WHICH 0: g_G (stride 256) -> g_U (256 cols)
// WHICH 1: g_U+128 (stride 256) -> g_V (128 cols)
// WHICH 2: g_Fb+40 (stride 120) -> g_Rb (80 cols)
// WHICH 3: g_Rb+40 (stride 80)  -> g_Sb (40 cols)
template <int NV4, int WHICH>
__global__ __launch_bounds__(256) void k_spmm(int n) {
    const float* __restrict__ in =
        (WHICH == 0) ? g_G : (WHICH == 1) ? (g_U + 128)
        : (WHICH == 2) ? (g_Fb + NCLS) : (g_Rb + NCLS);
    float* __restrict__ out =
        (WHICH == 0) ? g_U : (WHICH == 1) ? g_V : (WHICH == 2) ? g_Rb : g_Sb;
    constexpr int istride = (WHICH == 0) ? 256 : (WHICH == 1) ? 256
                            : (WHICH == 2) ? 120 : 80;
    constexpr int ostride = (WHICH == 0) ? 256 : (WHICH == 1) ? 128
                            : (WHICH == 2) ? 80 : 40;

    int w = (blockIdx.x * blockDim.x + threadIdx.x) >> 5;
    int lane = threadIdx.x & 31;
    if (w >= n) return;
    float di = g_dinv[w];
    constexpr int IT = (NV4 + 31) / 32;
    float4 acc[IT];
    const float4* xr = (const float4*)(in + (size_t)w * istride);
    #pragma unroll
    for (int t = 0; t < IT; t++) {
        int c = lane + 32 * t;
        if ((NV4 % 32 == 0) || c < NV4) {
            float4 v = xr[c];
            acc[t] = make_float4(di * v.x, di * v.y, di * v.z, di * v.w);
        } else {
            acc[t] = make_float4(0, 0, 0, 0);
        }
    }
    int jb = g_off[w], je = g_off[w + 1];
    int2 nxt = make_int2(0, 0);
    if (jb < je) nxt = g_csrw[jb];
    for (int j = jb; j < je; j++) {
        int2 cur = nxt;
        if (j + 1 < je) nxt = g_csrw[j + 1];
        int s = cur.x;
        float ws = __int_as_float(cur.y);
        const float4* xs = (const float4*)(in + (size_t)s * istride);
        #pragma unroll
        for (int t = 0; t < IT; t++) {
            int c = lane + 32 * t;
            if ((NV4 % 32 == 0) || c < NV4) {
                float4 v = __ldg(&xs[c]);
                acc[t].x += ws * v.x;
                acc[t].y += ws * v.y;
                acc[t].z += ws * v.z;
                acc[t].w += ws * v.w;
            }
        }
    }
    float4* o = (float4*)(out + (size_t)w * ostride);
    #pragma unroll
    for (int t = 0; t < IT; t++) {
        int c = lane + 32 * t;
        if ((NV4 % 32 == 0) || c < NV4)
            o[c] = make_float4(di * acc[t].x, di * acc[t].y, di * acc[t].z, di * acc[t].w);
    }
}

// ---------------- h cols 128..383 = relu(U/V + b1) -> bf16 hi/lo ----------------
__global__ void k_buildh(const float* __restrict__ b1, int n) {
    int idx = blockIdx.x * blockDim.x + threadIdx.x;
    if (idx >= n * 128) return;
    int r = idx >> 7, c2 = idx & 127;
    int c = c2 * 2;
    float2 v;
    if (c < 128)
        v = *(const float2*)&g_U[(size_t)r * 256 + c];
    else
        v = *(const float2*)&g_V[(size_t)r * 128 + (c - 128)];
    int col = 128 + c;
    float2 bb = *(const float2*)&b1[col];
    float v0 = fmaxf(v.x + bb.x, 0.f);
    float v1 = fmaxf(v.y + bb.y, 0.f);
    __nv_bfloat16 h0, h1, l0, l1;
    bf16split(v0, h0, l0);
    bf16split(v1, h1, l1);
    *(__nv_bfloat162*)&g_hhi[(size_t)r * 384 + col] = __halves2bfloat162(h0, h1);
    *(__nv_bfloat162*)&g_hlo[(size_t)r * 384 + col] = __halves2bfloat162(l0, l1);
}

// ---------------- final: gather blocks + b2, log_softmax over 120 ----------------
__global__ __launch_bounds__(256) void k_lsm(const float* __restrict__ b2,
                                             float* __restrict__ out, int n) {
    int w = (blockIdx.x * blockDim.x + threadIdx.x) >> 5;
    int lane = threadIdx.x & 31;
    if (w >= n) return;
    float4 v = make_float4(0, 0, 0, 0);
    bool act = lane < 30;
    if (act) {
        if (lane < 10)
            v = ((const float4*)g_Fb)[(size_t)w * 30 + lane];
        else if (lane < 20)
            v = ((const float4*)g_Rb)[(size_t)w * 20 + (lane - 10)];
        else
            v = ((const float4*)g_Sb)[(size_t)w * 10 + (lane - 20)];
        float4 bb = ((const float4*)b2)[lane];
        v.x += bb.x; v.y += bb.y; v.z += bb.z; v.w += bb.w;
    }
    float m = act ? fmaxf(fmaxf(v.x, v.y), fmaxf(v.z, v.w)) : -INFINITY;
    #pragma unroll
    for (int o = 16; o > 0; o >>= 1) m = fmaxf(m, __shfl_xor_sync(0xffffffffu, m, o));
    float s = 0.0f;
    if (act) s = expf(v.x - m) + expf(v.y - m) + expf(v.z - m) + expf(v.w - m);
    #pragma unroll
    for (int o = 16; o > 0; o >>= 1) s += __shfl_xor_sync(0xffffffffu, s, o);
    float lse = m + logf(s);
    if (act) {
        float4 r = make_float4(v.x - lse, v.y - lse, v.z - lse, v.w - lse);
        ((float4*)out)[(size_t)w * 30 + lane] = r;
    }
}

// ---------------- launch ----------------
extern "C" void kernel_launch(void* const* d_in, const int* in_sizes, int n_in,
                              void* d_out, int out_size) {
    const float* x = (const float*)d_in[0];
    const void* ei = d_in[1];
    const float* W1_0 = (const float*)d_in[2];
    const float* W1_1 = (const float*)d_in[3];
    const float* W1_2 = (const float*)d_in[4];
    const float* b1 = (const float*)d_in[5];
    const float* W2_0 = (const float*)d_in[6];
    const float* W2_1 = (const float*)d_in[7];
    const float* W2_2 = (const float*)d_in[8];
    const float* b2 = (const float*)d_in[9];
    float* out = (float*)d_out;

    int n = in_sizes[0] / FIN;  // 50000
    int e = in_sizes[1] / 2;    // 800000

    cudaFuncSetAttribute(k_mma<1>, cudaFuncAttributeMaxDynamicSharedMemorySize, SMEMSZ);
    cudaFuncSetAttribute(k_mma<2>, cudaFuncAttributeMaxDynamicSharedMemorySize, SMEMSZ);

    // graph preprocessing
    k_detect<<<1, 256>>>((const int2*)ei, e);
    k_convert<<<(e + 255) / 256, 256>>>(ei, e);
    k_init<<<(n + 255) / 256, 256>>>(n);
    k_deg<<<(e + 255) / 256, 256>>>(e);
    k_dinv<<<(n + 255) / 256, 256>>>(n);
    k_scan<<<1, 1024>>>(n, e);
    k_scatter<<<(e + 255) / 256, 256>>>(e);

    // operand conversion
    k_xsplit<<<(n * FIN / 4 + 255) / 256, 256>>>(x, n * FIN / 4);
    k_w1t<<<(384 * 256 + 255) / 256, 256>>>(W1_0, W1_1, W1_2);
    k_w2t<<<(120 * 384 + 255) / 256, 256>>>(W2_0, W2_1, W2_2);

    int mt = (n + 127) / 128;

    // layer 1: [h0 | G] = x @ [W0|W1|W2]
    k_mma<1><<<dim3(3, mt), 256, SMEMSZ>>>(b1, n);
    {
        int blocks = (n + 7) / 8;
        k_spmm<64, 0><<<blocks, 256>>>(n);  // U = P(G)
        k_spmm<32, 1><<<blocks, 256>>>(n);  // V = P(U[:,128:256])
    }
    k_buildh<<<(n * 128 + 255) / 256, 256>>>(b1, n);

    // layer 2: F = h @ [W0|W1|W2]
    k_mma<2><<<dim3(1, mt), 256, SMEMSZ>>>(b1, n);
    {
        int blocks = (n + 7) / 8;
        k_spmm<20, 2><<<blocks, 256>>>(n);  // R = P(F[:,40:120])
        k_spmm<10, 3><<<blocks, 256>>>(n);  // S = P(R[:,40:80])
    }
    k_lsm<<<(n + 7) / 8, 256>>>(b2, out, n);
}

// round 5
// speedup vs baseline: 1.4665x; 1.1065x over previous
#include <cuda_runtime.h>
#include <cuda_bf16.h>
#include <cuda_fp16.h>
#include <math.h>
#include <stdint.h>

#define NN 50000
#define EE 800000
#define FIN 256
#define HID 128
#define NCLS 40

// ---------------- scratch (device globals; no allocation allowed) ----------------
__device__ int   g_is64;
__device__ int   g_dst[EE];
__device__ int   g_deg[NN];
__device__ float g_dinv[NN];
__device__ int   g_off[NN + 1];
__device__ int   g_cursor[NN];
__device__ __align__(16) int2  g_csrw[EE];  // (src, dinv[src] bits)

__device__ __align__(16) __nv_bfloat16 g_xhi[(size_t)NN * FIN];
__device__ __align__(16) __nv_bfloat16 g_xlo[(size_t)NN * FIN];
__device__ __align__(16) __nv_bfloat16 g_w1t_hi[384 * 256];   // [N=384][K=256]
__device__ __align__(16) __nv_bfloat16 g_w1t_lo[384 * 256];
__device__ __align__(16) __nv_bfloat16 g_w2t_hi[120 * 384];   // [N=120][K=384]
__device__ __align__(16) __nv_bfloat16 g_w2t_lo[120 * 384];
__device__ __align__(16) __nv_bfloat16 g_hhi[(size_t)NN * 384];
__device__ __align__(16) __nv_bfloat16 g_hlo[(size_t)NN * 384];

// fp16 gather buffers for the SpMM chain
__device__ __align__(16) __half g_Gh[(size_t)NN * 256];  // x@[W1|W2]
__device__ __align__(16) __half g_Uh[(size_t)NN * 128];  // U[:,128:256] = P(x)@W2
__device__ __align__(16) __half g_Fh[(size_t)NN * 80];   // F[:,40:120]
__device__ __align__(16) __half g_Rh[(size_t)NN * 40];   // R[:,40:80]

__device__ __align__(16) float g_Fb[(size_t)NN * 120];   // fp32 for log_softmax
__device__ __align__(16) float g_Rb[(size_t)NN * 80];
__device__ __align__(16) float g_Sb[(size_t)NN * 40];

// ---------------- helpers ----------------
__device__ __forceinline__ uint32_t smem_u32(const void* p) {
    uint32_t a;
    asm("{ .reg .u64 t; cvta.to.shared.u64 t, %1; cvt.u32.u64 %0, t; }" : "=r"(a) : "l"(p));
    return a;
}

__device__ __forceinline__ void ldm_x4(uint32_t* r, uint32_t addr) {
    asm volatile("ldmatrix.sync.aligned.m8n8.x4.shared.b16 {%0,%1,%2,%3}, [%4];"
                 : "=r"(r[0]), "=r"(r[1]), "=r"(r[2]), "=r"(r[3]) : "r"(addr));
}

__device__ __forceinline__ void mma_bf16(float* d, const uint32_t* a, uint32_t b0, uint32_t b1) {
    asm volatile(
        "mma.sync.aligned.m16n8k16.row.col.f32.bf16.bf16.f32 "
        "{%0,%1,%2,%3}, {%4,%5,%6,%7}, {%8,%9}, {%0,%1,%2,%3};"
        : "+f"(d[0]), "+f"(d[1]), "+f"(d[2]), "+f"(d[3])
        : "r"(a[0]), "r"(a[1]), "r"(a[2]), "r"(a[3]), "r"(b0), "r"(b1));
}

__device__ __forceinline__ void bf16split(float a, __nv_bfloat16& h, __nv_bfloat16& l) {
    h = __float2bfloat16_rn(a);
    l = __float2bfloat16_rn(a - __bfloat162float(h));
}

// ---------------- preprocessing ----------------
// all blocks zero g_deg; block 0 also detects edge_index dtype
__global__ void k_zerodetect(const int2* __restrict__ ei2, int n, int e) {
    int i = blockIdx.x * blockDim.x + threadIdx.x;
    if (i < n) g_deg[i] = 0;
    if (blockIdx.x == 0) {
        __shared__ int nonzero;
        if (threadIdx.x == 0) nonzero = 0;
        __syncthreads();
        int t = threadIdx.x;
        if (t < 256 && t < e) {
            int2 p = ei2[t];
            if (p.y != 0) atomicAdd(&nonzero, 1);
        }
        __syncthreads();
        if (threadIdx.x == 0) g_is64 = (nonzero == 0) ? 1 : 0;
    }
}

// convert dst to int32 + degree histogram
__global__ void k_convdeg(const void* __restrict__ ei, int e) {
    int t = blockIdx.x * blockDim.x + threadIdx.x;
    if (t >= e) return;
    int d;
    if (g_is64) d = (int)((const long long*)ei)[(size_t)e + t];
    else        d = ((const int*)ei)[e + t];
    g_dst[t] = d;
    atomicAdd(&g_deg[d], 1);
}

__global__ void k_dinv(int n) {
    int i = blockIdx.x * blockDim.x + threadIdx.x;
    if (i < n) g_dinv[i] = rsqrtf((float)(g_deg[i] + 1));  // +1 self loop
}

__global__ __launch_bounds__(1024) void k_scan(int n, int e_total) {
    __shared__ int wsum[32];
    int tid = threadIdx.x;
    int lane = tid & 31, wid = tid >> 5;
    int chunk = (n + 1023) / 1024;
    int b = tid * chunk;
    int en = b + chunk; if (en > n) en = n;
    int s = 0;
    for (int i = b; i < en; i++) s += g_deg[i];
    int v = s;
    #pragma unroll
    for (int o = 1; o < 32; o <<= 1) {
        int t = __shfl_up_sync(0xffffffffu, v, o);
        if (lane >= o) v += t;
    }
    if (lane == 31) wsum[wid] = v;
    __syncthreads();
    if (wid == 0) {
        int w = wsum[lane];
        #pragma unroll
        for (int o = 1; o < 32; o <<= 1) {
            int t = __shfl_up_sync(0xffffffffu, w, o);
            if (lane >= o) w += t;
        }
        wsum[lane] = w;
    }
    __syncthreads();
    int run = (v - s) + (wid ? wsum[wid - 1] : 0);
    for (int i = b; i < en; i++) {
        g_off[i] = run;
        g_cursor[i] = run;
        run += g_deg[i];
    }
    if (tid == 0) g_off[n] = e_total;
}

__global__ void k_scatter(const void* __restrict__ ei, int e) {
    int t = blockIdx.x * blockDim.x + threadIdx.x;
    if (t >= e) return;
    int s;
    if (g_is64) s = (int)((const long long*)ei)[t];
    else        s = ((const int*)ei)[t];
    int d = g_dst[t];
    int p = atomicAdd(&g_cursor[d], 1);
    g_csrw[p] = make_int2(s, __float_as_int(g_dinv[s]));
}

// ---------------- data conversion ----------------
__global__ void k_xsplit(const float* __restrict__ x, int total4) {
    int i = blockIdx.x * blockDim.x + threadIdx.x;
    if (i >= total4) return;
    float4 v = ((const float4*)x)[i];
    __nv_bfloat16 h0, h1, h2, h3, l0, l1, l2, l3;
    bf16split(v.x, h0, l0); bf16split(v.y, h1, l1);
    bf16split(v.z, h2, l2); bf16split(v.w, h3, l3);
    ((__nv_bfloat162*)g_xhi)[i * 2] = __halves2bfloat162(h0, h1);
    ((__nv_bfloat162*)g_xhi)[i * 2 + 1] = __halves2bfloat162(h2, h3);
    ((__nv_bfloat162*)g_xlo)[i * 2] = __halves2bfloat162(l0, l1);
    ((__nv_bfloat162*)g_xlo)[i * 2 + 1] = __halves2bfloat162(l2, l3);
}

__global__ void k_w1t(const float* __restrict__ w0, const float* __restrict__ w1,
                      const float* __restrict__ w2) {
    int g = blockIdx.x * blockDim.x + threadIdx.x;
    if (g >= 384 * 256) return;
    int n = g / 256, k = g % 256;
    const float* w = (n < 128) ? w0 : (n < 256) ? w1 : w2;
    float v = w[k * 128 + (n & 127)];
    __nv_bfloat16 h, l;
    bf16split(v, h, l);
    g_w1t_hi[g] = h;
    g_w1t_lo[g] = l;
}

__global__ void k_w2t(const float* __restrict__ w0, const float* __restrict__ w1,
                      const float* __restrict__ w2) {
    int g = blockIdx.x * blockDim.x + threadIdx.x;
    if (g >= 120 * 384) return;
    int n = g / 384, k = g % 384;
    const float* w = (n < 40) ? w0 : (n < 80) ? w1 : w2;
    float v = w[k * 40 + (n % 40)];
    __nv_bfloat16 h, l;
    bf16split(v, h, l);
    g_w2t_hi[g] = h;
    g_w2t_lo[g] = l;
}

// ---------------- mma.sync GEMM (bf16 3-split) ----------------
#define SPITCH 72
#define OFF_AH 0
#define OFF_AL (128 * SPITCH)
#define OFF_BH (2 * 128 * SPITCH)
#define OFF_BL (3 * 128 * SPITCH)
#define SMEMSZ (4 * 128 * SPITCH * 2)  // 73728 bytes

__device__ __forceinline__ void ld_tile_sm(__nv_bfloat16* dst, const __nv_bfloat16* __restrict__ src,
                                           int row0, int validRows, int pitch, int k0, int tid) {
    #pragma unroll
    for (int it = 0; it < 4; it++) {
        int slot = tid + it * 256;  // 1024 slots = 128 rows x 8 float4
        int row = slot >> 3, q = slot & 7;
        float4 v = make_float4(0.f, 0.f, 0.f, 0.f);
        if (row < validRows)
            v = *reinterpret_cast<const float4*>(src + (size_t)(row0 + row) * pitch + k0 + q * 8);
        *reinterpret_cast<float4*>(dst + row * SPITCH + q * 8) = v;
    }
}

template <int LAYER>
__global__ __launch_bounds__(256) void k_mma(const float* __restrict__ b1, int M) {
    constexpr int K = (LAYER == 1) ? 256 : 384;
    constexpr int CH = K / 64;
    constexpr int APITCH = (LAYER == 1) ? 256 : 384;
    constexpr int BROWS = (LAYER == 1) ? 128 : 120;

    extern __shared__ __align__(16) __nv_bfloat16 sm[];
    uint32_t sbase = smem_u32(sm);

    int tid = threadIdx.x;
    int warp = tid >> 5, lane = tid & 31;
    int wm = warp & 3, wn = warp >> 2;  // 4 x 2 warp grid
    int rowSel = lane & 15;
    int kSel = (lane >> 4) << 3;

    int bm = blockIdx.y * 128, bn = blockIdx.x * 128;
    int rowsA = M - bm; if (rowsA > 128) rowsA = 128;

    const __nv_bfloat16* Ah = (LAYER == 1) ? g_xhi : g_hhi;
    const __nv_bfloat16* Al = (LAYER == 1) ? g_xlo : g_hlo;
    const __nv_bfloat16* Bh = (LAYER == 1) ? g_w1t_hi : g_w2t_hi;
    const __nv_bfloat16* Bl = (LAYER == 1) ? g_w1t_lo : g_w2t_lo;

    float acc[2][8][4];
    #pragma unroll
    for (int i = 0; i < 2; i++)
        #pragma unroll
        for (int j = 0; j < 8; j++)
            #pragma unroll
            for (int q = 0; q < 4; q++) acc[i][j][q] = 0.f;

    for (int c = 0; c < CH; c++) {
        int k0 = c * 64;
        ld_tile_sm(sm + OFF_AH, Ah, bm, rowsA, APITCH, k0, tid);
        ld_tile_sm(sm + OFF_AL, Al, bm, rowsA, APITCH, k0, tid);
        ld_tile_sm(sm + OFF_BH, Bh, bn, BROWS, K, k0, tid);
        ld_tile_sm(sm + OFF_BL, Bl, bn, BROWS, K, k0, tid);
        __syncthreads();
        #pragma unroll
        for (int kb = 0; kb < 64; kb += 16) {
            uint32_t aH[2][4], aL[2][4];
            #pragma unroll
            for (int i = 0; i < 2; i++) {
                uint32_t rowA = wm * 32 + i * 16 + rowSel;
                ldm_x4(aH[i], sbase + 2u * (OFF_AH + rowA * SPITCH + kb + kSel));
                ldm_x4(aL[i], sbase + 2u * (OFF_AL + rowA * SPITCH + kb + kSel));
            }
            #pragma unroll
            for (int jj = 0; jj < 4; jj++) {
                uint32_t bH[4], bL[4];
                uint32_t rowB = wn * 64 + jj * 16 + rowSel;
                ldm_x4(bH, sbase + 2u * (OFF_BH + rowB * SPITCH + kb + kSel));
                ldm_x4(bL, sbase + 2u * (OFF_BL + rowB * SPITCH + kb + kSel));
                #pragma unroll
                for (int i = 0; i < 2; i++) {
                    mma_bf16(acc[i][2 * jj], aH[i], bH[0], bH[2]);
                    mma_bf16(acc[i][2 * jj], aL[i], bH[0], bH[2]);
                    mma_bf16(acc[i][2 * jj], aH[i], bL[0], bL[2]);
                    mma_bf16(acc[i][2 * jj + 1], aH[i], bH[1], bH[3]);
                    mma_bf16(acc[i][2 * jj + 1], aL[i], bH[1], bH[3]);
                    mma_bf16(acc[i][2 * jj + 1], aH[i], bL[1], bL[3]);
                }
            }
        }
        __syncthreads();
    }

    // epilogue — fragment (m16n8): rows g, g+8; cols tg*2, tg*2+1
    int g = lane >> 2, tg = lane & 3;
    int m0 = bm + wm * 32;
    int nb = wn * 64;
    #pragma unroll
    for (int i = 0; i < 2; i++) {
        int r0 = m0 + i * 16 + g;
        int r1 = r0 + 8;
        #pragma unroll
        for (int j = 0; j < 8; j++) {
            int cl = nb + j * 8 + tg * 2;  // local col in [0,128)
            float2 v0 = make_float2(acc[i][j][0], acc[i][j][1]);
            float2 v1 = make_float2(acc[i][j][2], acc[i][j][3]);
            if (LAYER == 1) {
                if (blockIdx.x == 0) {
                    // h[:,0:128] = relu(D + b1) -> bf16 hi/lo
                    float2 bb = *(const float2*)&b1[cl];
                    if (r0 < M) {
                        float a0 = fmaxf(v0.x + bb.x, 0.f), a1 = fmaxf(v0.y + bb.y, 0.f);
                        __nv_bfloat16 h0, h1, l0, l1;
                        bf16split(a0, h0, l0); bf16split(a1, h1, l1);
                        *(__nv_bfloat162*)&g_hhi[(size_t)r0 * 384 + cl] = __halves2bfloat162(h0, h1);
                        *(__nv_bfloat162*)&g_hlo[(size_t)r0 * 384 + cl] = __halves2bfloat162(l0, l1);
                    }
                    if (r1 < M) {
                        float a0 = fmaxf(v1.x + bb.x, 0.f), a1 = fmaxf(v1.y + bb.y, 0.f);
                        __nv_bfloat16 h0, h1, l0, l1;
                        bf16split(a0, h0, l0); bf16split(a1, h1, l1);
                        *(__nv_bfloat162*)&g_hhi[(size_t)r1 * 384 + cl] = __halves2bfloat162(h0, h1);
                        *(__nv_bfloat162*)&g_hlo[(size_t)r1 * 384 + cl] = __halves2bfloat162(l0, l1);
                    }
                } else {
                    int cg = (blockIdx.x - 1) * 128 + cl;  // col in G [0,256)
                    if (r0 < M)
                        *(__half2*)&g_Gh[(size_t)r0 * 256 + cg] = __floats2half2_rn(v0.x, v0.y);
                    if (r1 < M)
                        *(__half2*)&g_Gh[(size_t)r1 * 256 + cg] = __floats2half2_rn(v1.x, v1.y);
                }
            } else {
                if (cl < 120) {
                    if (r0 < M) {
                        *(float2*)&g_Fb[(size_t)r0 * 120 + cl] = v0;
                        if (cl >= 40)
                            *(__half2*)&g_Fh[(size_t)r0 * 80 + (cl - 40)] = __floats2half2_rn(v0.x, v0.y);
                    }
                    if (r1 < M) {
                        *(float2*)&g_Fb[(size_t)r1 * 120 + cl] = v1;
                        if (cl >= 40)
                            *(__half2*)&g_Fh[(size_t)r1 * 80 + (cl - 40)] = __floats2half2_rn(v1.x, v1.y);
                    }
                }
            }
        }
    }
}

// ---------------- SpMM (fp16 gather, fp32 accumulate): one warp per row ----------------
// WHICH 0: g_Gh(256) -> h[:,128:256] (bf16 hi/lo, relu+b1) + g_Uh(128, fp16)
// WHICH 1: g_Uh(128) -> h[:,256:384] (bf16 hi/lo, relu+b1)
// WHICH 2: g_Fh(80)  -> g_Rb(80, fp32) + g_Rh(40, fp16 from cols 40..79)
// WHICH 3: g_Rh(40)  -> g_Sb(40, fp32)
template <int NH, int WHICH>
__global__ __launch_bounds__(256) void k_spmmh(const float* __restrict__ b1, int n) {
    constexpr int IT = (NH + 127) / 128;
    const __half* __restrict__ in =
        (WHICH == 0) ? g_Gh : (WHICH == 1) ? g_Uh : (WHICH == 2) ? g_Fh : g_Rh;

    int w = (blockIdx.x * blockDim.x + threadIdx.x) >> 5;
    int lane = threadIdx.x & 31;
    if (w >= n) return;
    float di = g_dinv[w];

    float4 acc[IT];
    #pragma unroll
    for (int t = 0; t < IT; t++) {
        int c = t * 128 + lane * 4;
        acc[t] = make_float4(0, 0, 0, 0);
        if (c < NH) {
            uint2 u = *(const uint2*)(in + (size_t)w * NH + c);
            float2 f0 = __half22float2(*(__half2*)&u.x);
            float2 f1 = __half22float2(*(__half2*)&u.y);
            acc[t] = make_float4(di * f0.x, di * f0.y, di * f1.x, di * f1.y);
        }
    }
    int jb = g_off[w], je = g_off[w + 1];
    int2 nxt = make_int2(0, 0);
    if (jb < je) nxt = g_csrw[jb];
    for (int j = jb; j < je; j++) {
        int2 cur = nxt;
        if (j + 1 < je) nxt = g_csrw[j + 1];
        int s = cur.x;
        float ws = __int_as_float(cur.y);
        #pragma unroll
        for (int t = 0; t < IT; t++) {
            int c = t * 128 + lane * 4;
            if (c < NH) {
                uint2 u = __ldg((const uint2*)(in + (size_t)s * NH + c));
                float2 f0 = __half22float2(*(__half2*)&u.x);
                float2 f1 = __half22float2(*(__half2*)&u.y);
                acc[t].x += ws * f0.x;
                acc[t].y += ws * f0.y;
                acc[t].z += ws * f1.x;
                acc[t].w += ws * f1.y;
            }
        }
    }
    #pragma unroll
    for (int t = 0; t < IT; t++) {
        int c = t * 128 + lane * 4;
        if (c >= NH) continue;
        float4 ov = make_float4(di * acc[t].x, di * acc[t].y, di * acc[t].z, di * acc[t].w);
        if (WHICH == 0) {
            if (c < 128) {
                int col = 128 + c;
                float4 bb = *(const float4*)&b1[col];
                float a0 = fmaxf(ov.x + bb.x, 0.f), a1 = fmaxf(ov.y + bb.y, 0.f);
                float a2 = fmaxf(ov.z + bb.z, 0.f), a3 = fmaxf(ov.w + bb.w, 0.f);
                __nv_bfloat16 h0, h1, h2, h3, l0, l1, l2, l3;
                bf16split(a0, h0, l0); bf16split(a1, h1, l1);
                bf16split(a2, h2, l2); bf16split(a3, h3, l3);
                *(__nv_bfloat162*)&g_hhi[(size_t)w * 384 + col] = __halves2bfloat162(h0, h1);
                *(__nv_bfloat162*)&g_hhi[(size_t)w * 384 + col + 2] = __halves2bfloat162(h2, h3);
                *(__nv_bfloat162*)&g_hlo[(size_t)w * 384 + col] = __halves2bfloat162(l0, l1);
                *(__nv_bfloat162*)&g_hlo[(size_t)w * 384 + col + 2] = __halves2bfloat162(l2, l3);
            } else {
                __half2 q0 = __floats2half2_rn(ov.x, ov.y);
                __half2 q1 = __floats2half2_rn(ov.z, ov.w);
                uint2 u;
                u.x = *(uint32_t*)&q0;
                u.y = *(uint32_t*)&q1;
                *(uint2*)&g_Uh[(size_t)w * 128 + (c - 128)] = u;
            }
        } else if (WHICH == 1) {
            int col = 256 + c;
            float4 bb = *(const float4*)&b1[col];
            float a0 = fmaxf(ov.x + bb.x, 0.f), a1 = fmaxf(ov.y + bb.y, 0.f);
            float a2 = fmaxf(ov.z + bb.z, 0.f), a3 = fmaxf(ov.w + bb.w, 0.f);
            __nv_bfloat16 h0, h1, h2, h3, l0, l1, l2, l3;
            bf16split(a0, h0, l0); bf16split(a1, h1, l1);
            bf16split(a2, h2, l2); bf16split(a3, h3, l3);
            *(__nv_bfloat162*)&g_hhi[(size_t)w * 384 + col] = __halves2bfloat162(h0, h1);
            *(__nv_bfloat162*)&g_hhi[(size_t)w * 384 + col + 2] = __halves2bfloat162(h2, h3);
            *(__nv_bfloat162*)&g_hlo[(size_t)w * 384 + col] = __halves2bfloat162(l0, l1);
            *(__nv_bfloat162*)&g_hlo[(size_t)w * 384 + col + 2] = __halves2bfloat162(l2, l3);
        } else if (WHICH == 2) {
            *(float4*)&g_Rb[(size_t)w * 80 + c] = ov;
            if (c >= 40) {
                __half2 q0 = __floats2half2_rn(ov.x, ov.y);
                __half2 q1 = __floats2half2_rn(ov.z, ov.w);
                uint2 u;
                u.x = *(uint32_t*)&q0;
                u.y = *(uint32_t*)&q1;
                *(uint2*)&g_Rh[(size_t)w * 40 + (c - 40)] = u;
            }
        } else {
            *(float4*)&g_Sb[(size_t)w * 40 + c] = ov;
        }
    }
}

// ---------------- final: gather blocks + b2, log_softmax over 120 ----------------
__global__ __launch_bounds__(256) void k_lsm(const float* __restrict__ b2,
                                             float* __restrict__ out, int n) {
    int w = (blockIdx.x * blockDim.x + threadIdx.x) >> 5;
    int lane = threadIdx.x & 31;
    if (w >= n) return;
    float4 v = make_float4(0, 0, 0, 0);
    bool act = lane < 30;
    if (act) {
        if (lane < 10)
            v = ((const float4*)g_Fb)[(size_t)w * 30 + lane];
        else if (lane < 20)
            v = ((const float4*)g_Rb)[(size_t)w * 20 + (lane - 10)];
        else
            v = ((const float4*)g_Sb)[(size_t)w * 10 + (lane - 20)];
        float4 bb = ((const float4*)b2)[lane];
        v.x += bb.x; v.y += bb.y; v.z += bb.z; v.w += bb.w;
    }
    float m = act ? fmaxf(fmaxf(v.x, v.y), fmaxf(v.z, v.w)) : -INFINITY;
    #pragma unroll
    for (int o = 16; o > 0; o >>= 1) m = fmaxf(m, __shfl_xor_sync(0xffffffffu, m, o));
    float s = 0.0f;
    if (act) s = expf(v.x - m) + expf(v.y - m) + expf(v.z - m) + expf(v.w - m);
    #pragma unroll
    for (int o = 16; o > 0; o >>= 1) s += __shfl_xor_sync(0xffffffffu, s, o);
    float lse = m + logf(s);
    if (act) {
        float4 r = make_float4(v.x - lse, v.y - lse, v.z - lse, v.w - lse);
        ((float4*)out)[(size_t)w * 30 + lane] = r;
    }
}

// ---------------- launch ----------------
extern "C" void kernel_launch(void* const* d_in, const int* in_sizes, int n_in,
                              void* d_out, int out_size) {
    const float* x = (const float*)d_in[0];
    const void* ei = d_in[1];
    const float* W1_0 = (const float*)d_in[2];
    const float* W1_1 = (const float*)d_in[3];
    const float* W1_2 = (const float*)d_in[4];
    const float* b1 = (const float*)d_in[5];
    const float* W2_0 = (const float*)d_in[6];
    const float* W2_1 = (const float*)d_in[7];
    const float* W2_2 = (const float*)d_in[8];
    const float* b2 = (const float*)d_in[9];
    float* out = (float*)d_out;

    int n = in_sizes[0] / FIN;  // 50000
    int e = in_sizes[1] / 2;    // 800000

    cudaFuncSetAttribute(k_mma<1>, cudaFuncAttributeMaxDynamicSharedMemorySize, SMEMSZ);
    cudaFuncSetAttribute(k_mma<2>, cudaFuncAttributeMaxDynamicSharedMemorySize, SMEMSZ);

    // graph preprocessing
    k_zerodetect<<<(n + 255) / 256, 256>>>((const int2*)ei, n, e);
    k_convdeg<<<(e + 255) / 256, 256>>>(ei, e);
    k_dinv<<<(n + 255) / 256, 256>>>(n);
    k_scan<<<1, 1024>>>(n, e);
    k_scatter<<<(e + 255) / 256, 256>>>(ei, e);

    // operand conversion
    k_xsplit<<<(n * FIN / 4 + 255) / 256, 256>>>(x, n * FIN / 4);
    k_w1t<<<(384 * 256 + 255) / 256, 256>>>(W1_0, W1_1, W1_2);
    k_w2t<<<(120 * 384 + 255) / 256, 256>>>(W2_0, W2_1, W2_2);

    int mt = (n + 127) / 128;
    int sb = (n + 7) / 8;

    // layer 1: [h0 | Gh] = x @ [W0|W1|W2]
    k_mma<1><<<dim3(3, mt), 256, SMEMSZ>>>(b1, n);
    k_spmmh<256, 0><<<sb, 256>>>(b1, n);  // U = P(G): h[:,128:256] + Uh
    k_spmmh<128, 1><<<sb, 256>>>(b1, n);  // V = P(Uh): h[:,256:384]

    // layer 2: F = h @ [W0|W1|W2]
    k_mma<2><<<dim3(1, mt), 256, SMEMSZ>>>(b1, n);
    k_spmmh<80, 2><<<sb, 256>>>(b1, n);   // R = P(Fh)
    k_spmmh<40, 3><<<sb, 256>>>(b1, n);   // S = P(Rh)

    k_lsm<<<(n + 7) / 8, 256>>>(b2, out, n);
}

// round 8
// speedup vs baseline: 1.7203x; 1.1731x over previous
#include <cuda_runtime.h>
#include <cuda_bf16.h>
#include <cuda_fp16.h>
#include <math.h>
#include <stdint.h>

#define NN 50000
#define EE 800000
#define FIN 256
#define HID 128
#define NCLS 40

#define SCB 512
#define NSB ((NN + SCB - 1) / SCB)  // 98

// ---------------- scratch (device globals; no allocation allowed) ----------------
__device__ int   g_is64;
__device__ int   g_dst[EE];
__device__ int   g_deg[NN];
__device__ float g_dinv[NN];
__device__ int   g_off[NN + 1];
__device__ int   g_cursor[NN];
__device__ int   g_bsum[NSB];
__device__ __align__(16) int2  g_csrw[EE];  // (src, dinv[src] bits)

__device__ __align__(16) __nv_bfloat16 g_xhi[(size_t)NN * FIN];
__device__ __align__(16) __nv_bfloat16 g_xlo[(size_t)NN * FIN];
__device__ __align__(16) __nv_bfloat16 g_w1t_hi[384 * 256];   // [N=384][K=256]
__device__ __align__(16) __nv_bfloat16 g_w1t_lo[384 * 256];
__device__ __align__(16) __nv_bfloat16 g_w2t_hi[120 * 384];   // [N=120][K=384]
__device__ __align__(16) __nv_bfloat16 g_w2t_lo[120 * 384];
__device__ __align__(16) __nv_bfloat16 g_hhi[(size_t)NN * 384];
__device__ __align__(16) __nv_bfloat16 g_hlo[(size_t)NN * 384];

// fp16 gather buffers for the SpMM chain
__device__ __align__(16) __half g_Gh[(size_t)NN * 256];  // x@[W1|W2]
__device__ __align__(16) __half g_Uh[(size_t)NN * 128];  // U[:,128:256]
__device__ __align__(16) __half g_Fh[(size_t)NN * 80];   // F[:,40:120]
__device__ __align__(16) __half g_Rh[(size_t)NN * 40];   // R[:,40:80]

__device__ __align__(16) float g_Fb[(size_t)NN * 120];   // fp32 for log_softmax
__device__ __align__(16) float g_Rb[(size_t)NN * 80];
__device__ __align__(16) float g_Sb[(size_t)NN * 40];

// ---------------- helpers ----------------
__device__ __forceinline__ uint32_t smem_u32(const void* p) {
    uint32_t a;
    asm("{ .reg .u64 t; cvta.to.shared.u64 t, %1; cvt.u32.u64 %0, t; }" : "=r"(a) : "l"(p));
    return a;
}

__device__ __forceinline__ void ldm_x4(uint32_t* r, uint32_t addr) {
    asm volatile("ldmatrix.sync.aligned.m8n8.x4.shared.b16 {%0,%1,%2,%3}, [%4];"
                 : "=r"(r[0]), "=r"(r[1]), "=r"(r[2]), "=r"(r[3]) : "r"(addr));
}

__device__ __forceinline__ void mma_bf16(float* d, const uint32_t* a, uint32_t b0, uint32_t b1) {
    asm volatile(
        "mma.sync.aligned.m16n8k16.row.col.f32.bf16.bf16.f32 "
        "{%0,%1,%2,%3}, {%4,%5,%6,%7}, {%8,%9}, {%0,%1,%2,%3};"
        : "+f"(d[0]), "+f"(d[1]), "+f"(d[2]), "+f"(d[3])
        : "r"(a[0]), "r"(a[1]), "r"(a[2]), "r"(a[3]), "r"(b0), "r"(b1));
}

__device__ __forceinline__ void bf16split(float a, __nv_bfloat16& h, __nv_bfloat16& l) {
    h = __float2bfloat16_rn(a);
    l = __float2bfloat16_rn(a - __bfloat162float(h));
}

// ---------------- preprocessing ----------------
__global__ void k_zerodetect(const int2* __restrict__ ei2, int n, int e) {
    int i = blockIdx.x * blockDim.x + threadIdx.x;
    if (i < n) g_deg[i] = 0;
    if (blockIdx.x == 0) {
        __shared__ int nonzero;
        if (threadIdx.x == 0) nonzero = 0;
        __syncthreads();
        int t = threadIdx.x;
        if (t < 256 && t < e) {
            int2 p = ei2[t];
            if (p.y != 0) atomicAdd(&nonzero, 1);
        }
        __syncthreads();
        if (threadIdx.x == 0) g_is64 = (nonzero == 0) ? 1 : 0;
    }
}

__global__ void k_convdeg(const void* __restrict__ ei, int e) {
    int t = blockIdx.x * blockDim.x + threadIdx.x;
    if (t >= e) return;
    int d;
    if (g_is64) d = (int)((const long long*)ei)[(size_t)e + t];
    else        d = ((const int*)ei)[e + t];
    g_dst[t] = d;
    atomicAdd(&g_deg[d], 1);
}

__global__ void k_dinv(int n) {
    int i = blockIdx.x * blockDim.x + threadIdx.x;
    if (i < n) g_dinv[i] = rsqrtf((float)(g_deg[i] + 1));  // +1 self loop
}

// -------- hierarchical scan --------
// phase 1: per-block exclusive scan of g_deg, block sums to g_bsum
__global__ __launch_bounds__(SCB) void k_scan1(int n) {
    __shared__ int wsum[SCB / 32];
    int tid = threadIdx.x, lane = tid & 31, wid = tid >> 5;
    int i = blockIdx.x * SCB + tid;
    int v = (i < n) ? g_deg[i] : 0;
    int inc = v;
    #pragma unroll
    for (int o = 1; o < 32; o <<= 1) {
        int t = __shfl_up_sync(0xffffffffu, inc, o);
        if (lane >= o) inc += t;
    }
    if (lane == 31) wsum[wid] = inc;
    __syncthreads();
    if (wid == 0) {
        // ALL 32 lanes participate in the shuffle (mask is full); extra lanes carry 0
        int w = (lane < SCB / 32) ? wsum[lane] : 0;
        #pragma unroll
        for (int o = 1; o < SCB / 32; o <<= 1) {
            int t = __shfl_up_sync(0xffffffffu, w, o);
            if (lane >= o) w += t;
        }
        if (lane < SCB / 32) wsum[lane] = w;
    }
    __syncthreads();
    int ex = (inc - v) + (wid ? wsum[wid - 1] : 0);
    if (i < n) g_off[i] = ex;
    if (tid == SCB - 1) g_bsum[blockIdx.x] = ex + v;
}

// phase 2: single warp scans the NSB block sums (exclusive, in place)
__global__ void k_scan2() {
    int lane = threadIdx.x;
    int carry = 0;
    for (int b = 0; b < NSB; b += 32) {
        int idx = b + lane;
        int v = (idx < NSB) ? g_bsum[idx] : 0;
        int inc = v;
        #pragma unroll
        for (int o = 1; o < 32; o <<= 1) {
            int t = __shfl_up_sync(0xffffffffu, inc, o);
            if (lane >= o) inc += t;
        }
        int ex = carry + inc - v;
        if (idx < NSB) g_bsum[idx] = ex;
        carry += __shfl_sync(0xffffffffu, inc, 31);
    }
}

// phase 3: add block offsets, fill cursor, off[n]=e
__global__ void k_scan3(int n, int e_total) {
    int i = blockIdx.x * blockDim.x + threadIdx.x;
    if (i < n) {
        int o = g_off[i] + g_bsum[i / SCB];
        g_off[i] = o;
        g_cursor[i] = o;
    }
    if (i == 0) g_off[n] = e_total;
}

__global__ void k_scatter(const void* __restrict__ ei, int e) {
    int t = blockIdx.x * blockDim.x + threadIdx.x;
    if (t >= e) return;
    int s;
    if (g_is64) s = (int)((const long long*)ei)[t];
    else        s = ((const int*)ei)[t];
    int d = g_dst[t];
    int p = atomicAdd(&g_cursor[d], 1);
    g_csrw[p] = make_int2(s, __float_as_int(g_dinv[s]));
}

// ---------------- data conversion ----------------
__global__ void k_xsplit(const float* __restrict__ x, int total4) {
    int i = blockIdx.x * blockDim.x + threadIdx.x;
    if (i >= total4) return;
    float4 v = ((const float4*)x)[i];
    __nv_bfloat16 h0, h1, h2, h3, l0, l1, l2, l3;
    bf16split(v.x, h0, l0); bf16split(v.y, h1, l1);
    bf16split(v.z, h2, l2); bf16split(v.w, h3, l3);
    ((__nv_bfloat162*)g_xhi)[i * 2] = __halves2bfloat162(h0, h1);
    ((__nv_bfloat162*)g_xhi)[i * 2 + 1] = __halves2bfloat162(h2, h3);
    ((__nv_bfloat162*)g_xlo)[i * 2] = __halves2bfloat162(l0, l1);
    ((__nv_bfloat162*)g_xlo)[i * 2 + 1] = __halves2bfloat162(l2, l3);
}

// merged W1T + W2T transpose/split
__global__ void k_wsplit(const float* __restrict__ w10, const float* __restrict__ w11,
                         const float* __restrict__ w12, const float* __restrict__ w20,
                         const float* __restrict__ w21, const float* __restrict__ w22) {
    int g = blockIdx.x * blockDim.x + threadIdx.x;
    if (g < 384 * 256) {
        int n = g / 256, k = g % 256;
        const float* w = (n < 128) ? w10 : (n < 256) ? w11 : w12;
        float v = w[k * 128 + (n & 127)];
        __nv_bfloat16 h, l;
        bf16split(v, h, l);
        g_w1t_hi[g] = h;
        g_w1t_lo[g] = l;
    } else if (g < 384 * 256 + 120 * 384) {
        int g2 = g - 384 * 256;
        int n = g2 / 384, k = g2 % 384;
        const float* w = (n < 40) ? w20 : (n < 80) ? w21 : w22;
        float v = w[k * 40 + (n % 40)];
        __nv_bfloat16 h, l;
        bf16split(v, h, l);
        g_w2t_hi[g2] = h;
        g_w2t_lo[g2] = l;
    }
}

// ---------------- mma.sync GEMM (bf16 3-split) ----------------
#define SPITCH 72
#define OFF_AH 0
#define OFF_AL (128 * SPITCH)
#define OFF_BH (2 * 128 * SPITCH)
#define OFF_BL (3 * 128 * SPITCH)
#define SMEMSZ (4 * 128 * SPITCH * 2)  // 73728 bytes

__device__ __forceinline__ void ld_tile_sm(__nv_bfloat16* dst, const __nv_bfloat16* __restrict__ src,
                                           int row0, int validRows, int pitch, int k0, int tid) {
    #pragma unroll
    for (int it = 0; it < 4; it++) {
        int slot = tid + it * 256;
        int row = slot >> 3, q = slot & 7;
        float4 v = make_float4(0.f, 0.f, 0.f, 0.f);
        if (row < validRows)
            v = *reinterpret_cast<const float4*>(src + (size_t)(row0 + row) * pitch + k0 + q * 8);
        *reinterpret_cast<float4*>(dst + row * SPITCH + q * 8) = v;
    }
}

template <int LAYER>
__global__ __launch_bounds__(256) void k_mma(const float* __restrict__ b1, int M) {
    constexpr int K = (LAYER == 1) ? 256 : 384;
    constexpr int CH = K / 64;
    constexpr int APITCH = (LAYER == 1) ? 256 : 384;
    constexpr int BROWS = (LAYER == 1) ? 128 : 120;

    extern __shared__ __align__(16) __nv_bfloat16 sm[];
    uint32_t sbase = smem_u32(sm);

    int tid = threadIdx.x;
    int warp = tid >> 5, lane = tid & 31;
    int wm = warp & 3, wn = warp >> 2;
    int rowSel = lane & 15;
    int kSel = (lane >> 4) << 3;

    int bm = blockIdx.y * 128, bn = blockIdx.x * 128;
    int rowsA = M - bm; if (rowsA > 128) rowsA = 128;

    const __nv_bfloat16* Ah = (LAYER == 1) ? g_xhi : g_hhi;
    const __nv_bfloat16* Al = (LAYER == 1) ? g_xlo : g_hlo;
    const __nv_bfloat16* Bh = (LAYER == 1) ? g_w1t_hi : g_w2t_hi;
    const __nv_bfloat16* Bl = (LAYER == 1) ? g_w1t_lo : g_w2t_lo;

    float acc[2][8][4];
    #pragma unroll
    for (int i = 0; i < 2; i++)
        #pragma unroll
        for (int j = 0; j < 8; j++)
            #pragma unroll
            for (int q = 0; q < 4; q++) acc[i][j][q] = 0.f;

    for (int c = 0; c < CH; c++) {
        int k0 = c * 64;
        ld_tile_sm(sm + OFF_AH, Ah, bm, rowsA, APITCH, k0, tid);
        ld_tile_sm(sm + OFF_AL, Al, bm, rowsA, APITCH, k0, tid);
        ld_tile_sm(sm + OFF_BH, Bh, bn, BROWS, K, k0, tid);
        ld_tile_sm(sm + OFF_BL, Bl, bn, BROWS, K, k0, tid);
        __syncthreads();
        #pragma unroll
        for (int kb = 0; kb < 64; kb += 16) {
            uint32_t aH[2][4], aL[2][4];
            #pragma unroll
            for (int i = 0; i < 2; i++) {
                uint32_t rowA = wm * 32 + i * 16 + rowSel;
                ldm_x4(aH[i], sbase + 2u * (OFF_AH + rowA * SPITCH + kb + kSel));
                ldm_x4(aL[i], sbase + 2u * (OFF_AL + rowA * SPITCH + kb + kSel));
            }
            #pragma unroll
            for (int jj = 0; jj < 4; jj++) {
                uint32_t bH[4], bL[4];
                uint32_t rowB = wn * 64 + jj * 16 + rowSel;
                ldm_x4(bH, sbase + 2u * (OFF_BH + rowB * SPITCH + kb + kSel));
                ldm_x4(bL, sbase + 2u * (OFF_BL + rowB * SPITCH + kb + kSel));
                #pragma unroll
                for (int i = 0; i < 2; i++) {
                    mma_bf16(acc[i][2 * jj], aH[i], bH[0], bH[2]);
                    mma_bf16(acc[i][2 * jj], aL[i], bH[0], bH[2]);
                    mma_bf16(acc[i][2 * jj], aH[i], bL[0], bL[2]);
                    mma_bf16(acc[i][2 * jj + 1], aH[i], bH[1], bH[3]);
                    mma_bf16(acc[i][2 * jj + 1], aL[i], bH[1], bH[3]);
                    mma_bf16(acc[i][2 * jj + 1], aH[i], bL[1], bL[3]);
                }
            }
        }
        __syncthreads();
    }

    int g = lane >> 2, tg = lane & 3;
    int m0 = bm + wm * 32;
    int nb = wn * 64;
    #pragma unroll
    for (int i = 0; i < 2; i++) {
        int r0 = m0 + i * 16 + g;
        int r1 = r0 + 8;
        #pragma unroll
        for (int j = 0; j < 8; j++) {
            int cl = nb + j * 8 + tg * 2;
            float2 v0 = make_float2(acc[i][j][0], acc[i][j][1]);
            float2 v1 = make_float2(acc[i][j][2], acc[i][j][3]);
            if (LAYER == 1) {
                if (blockIdx.x == 0) {
                    float2 bb = *(const float2*)&b1[cl];
                    if (r0 < M) {
                        float a0 = fmaxf(v0.x + bb.x, 0.f), a1 = fmaxf(v0.y + bb.y, 0.f);
                        __nv_bfloat16 h0, h1, l0, l1;
                        bf16split(a0, h0, l0); bf16split(a1, h1, l1);
                        *(__nv_bfloat162*)&g_hhi[(size_t)r0 * 384 + cl] = __halves2bfloat162(h0, h1);
                        *(__nv_bfloat162*)&g_hlo[(size_t)r0 * 384 + cl] = __halves2bfloat162(l0, l1);
                    }
                    if (r1 < M) {
                        float a0 = fmaxf(v1.x + bb.x, 0.f), a1 = fmaxf(v1.y + bb.y, 0.f);
                        __nv_bfloat16 h0, h1, l0, l1;
                        bf16split(a0, h0, l0); bf16split(a1, h1, l1);
                        *(__nv_bfloat162*)&g_hhi[(size_t)r1 * 384 + cl] = __halves2bfloat162(h0, h1);
                        *(__nv_bfloat162*)&g_hlo[(size_t)r1 * 384 + cl] = __halves2bfloat162(l0, l1);
                    }
                } else {
                    int cg = (blockIdx.x - 1) * 128 + cl;
                    if (r0 < M)
                        *(__half2*)&g_Gh[(size_t)r0 * 256 + cg] = __floats2half2_rn(v0.x, v0.y);
                    if (r1 < M)
                        *(__half2*)&g_Gh[(size_t)r1 * 256 + cg] = __floats2half2_rn(v1.x, v1.y);
                }
            } else {
                if (cl < 120) {
                    if (r0 < M) {
                        *(float2*)&g_Fb[(size_t)r0 * 120 + cl] = v0;
                        if (cl >= 40)
                            *(__half2*)&g_Fh[(size_t)r0 * 80 + (cl - 40)] = __floats2half2_rn(v0.x, v0.y);
                    }
                    if (r1 < M) {
                        *(float2*)&g_Fb[(size_t)r1 * 120 + cl] = v1;
                        if (cl >= 40)
                            *(__half2*)&g_Fh[(size_t)r1 * 80 + (cl - 40)] = __floats2half2_rn(v1.x, v1.y);
                    }
                }
            }
        }
    }
}

// ---------------- SpMM (fp16 gather, fp32 accumulate): one warp per row ----------------
template <int NH, int WHICH>
__global__ __launch_bounds__(256) void k_spmmh(const float* __restrict__ b1, int n) {
    constexpr int IT = (NH + 127) / 128;
    const __half* __restrict__ in =
        (WHICH == 0) ? g_Gh : (WHICH == 1) ? g_Uh : (WHICH == 2) ? g_Fh : g_Rh;

    int w = (blockIdx.x * blockDim.x + threadIdx.x) >> 5;
    int lane = threadIdx.x & 31;
    if (w >= n) return;
    float di = g_dinv[w];

    float4 acc[IT];
    #pragma unroll
    for (int t = 0; t < IT; t++) {
        int c = t * 128 + lane * 4;
        acc[t] = make_float4(0, 0, 0, 0);
        if (c < NH) {
            uint2 u = *(const uint2*)(in + (size_t)w * NH + c);
            float2 f0 = __half22float2(*(__half2*)&u.x);
            float2 f1 = __half22float2(*(__half2*)&u.y);
            acc[t] = make_float4(di * f0.x, di * f0.y, di * f1.x, di * f1.y);
        }
    }
    int jb = g_off[w], je = g_off[w + 1];
    int2 nxt = make_int2(0, 0);
    if (jb < je) nxt = g_csrw[jb];
    for (int j = jb; j < je; j++) {
        int2 cur = nxt;
        if (j + 1 < je) nxt = g_csrw[j + 1];
        int s = cur.x;
        float ws = __int_as_float(cur.y);
        #pragma unroll
        for (int t = 0; t < IT; t++) {
            int c = t * 128 + lane * 4;
            if (c < NH) {
                uint2 u = __ldg((const uint2*)(in + (size_t)s * NH + c));
                float2 f0 = __half22float2(*(__half2*)&u.x);
                float2 f1 = __half22float2(*(__half2*)&u.y);
                acc[t].x += ws * f0.x;
                acc[t].y += ws * f0.y;
                acc[t].z += ws * f1.x;
                acc[t].w += ws * f1.y;
            }
        }
    }
    #pragma unroll
    for (int t = 0; t < IT; t++) {
        int c = t * 128 + lane * 4;
        if (c >= NH) continue;
        float4 ov = make_float4(di * acc[t].x, di * acc[t].y, di * acc[t].z, di * acc[t].w);
        if (WHICH == 0) {
            if (c < 128) {
                int col = 128 + c;
                float4 bb = *(const float4*)&b1[col];
                float a0 = fmaxf(ov.x + bb.x, 0.f), a1 = fmaxf(ov.y + bb.y, 0.f);
                float a2 = fmaxf(ov.z + bb.z, 0.f), a3 = fmaxf(ov.w + bb.w, 0.f);
                __nv_bfloat16 h0, h1, h2, h3, l0, l1, l2, l3;
                bf16split(a0, h0, l0); bf16split(a1, h1, l1);
                bf16split(a2, h2, l2); bf16split(a3, h3, l3);
                *(__nv_bfloat162*)&g_hhi[(size_t)w * 384 + col] = __halves2bfloat162(h0, h1);
                *(__nv_bfloat162*)&g_hhi[(size_t)w * 384 + col + 2] = __halves2bfloat162(h2, h3);
                *(__nv_bfloat162*)&g_hlo[(size_t)w * 384 + col] = __halves2bfloat162(l0, l1);
                *(__nv_bfloat162*)&g_hlo[(size_t)w * 384 + col + 2] = __halves2bfloat162(l2, l3);
            } else {
                __half2 q0 = __floats2half2_rn(ov.x, ov.y);
                __half2 q1 = __floats2half2_rn(ov.z, ov.w);
                uint2 u;
                u.x = *(uint32_t*)&q0;
                u.y = *(uint32_t*)&q1;
                *(uint2*)&g_Uh[(size_t)w * 128 + (c - 128)] = u;
            }
        } else if (WHICH == 1) {
            int col = 256 + c;
            float4 bb = *(const float4*)&b1[col];
            float a0 = fmaxf(ov.x + bb.x, 0.f), a1 = fmaxf(ov.y + bb.y, 0.f);
            float a2 = fmaxf(ov.z + bb.z, 0.f), a3 = fmaxf(ov.w + bb.w, 0.f);
            __nv_bfloat16 h0, h1, h2, h3, l0, l1, l2, l3;
            bf16split(a0, h0, l0); bf16split(a1, h1, l1);
            bf16split(a2, h2, l2); bf16split(a3, h3, l3);
            *(__nv_bfloat162*)&g_hhi[(size_t)w * 384 + col] = __halves2bfloat162(h0, h1);
            *(__nv_bfloat162*)&g_hhi[(size_t)w * 384 + col + 2] = __halves2bfloat162(h2, h3);
            *(__nv_bfloat162*)&g_hlo[(size_t)w * 384 + col] = __halves2bfloat162(l0, l1);
            *(__nv_bfloat162*)&g_hlo[(size_t)w * 384 + col + 2] = __halves2bfloat162(l2, l3);
        } else if (WHICH == 2) {
            *(float4*)&g_Rb[(size_t)w * 80 + c] = ov;
            if (c >= 40) {
                __half2 q0 = __floats2half2_rn(ov.x, ov.y);
                __half2 q1 = __floats2half2_rn(ov.z, ov.w);
                uint2 u;
                u.x = *(uint32_t*)&q0;
                u.y = *(uint32_t*)&q1;
                *(uint2*)&g_Rh[(size_t)w * 40 + (c - 40)] = u;
            }
        } else {
            *(float4*)&g_Sb[(size_t)w * 40 + c] = ov;
        }
    }
}

// ---------------- final: gather blocks + b2, log_softmax over 120 ----------------
__global__ __launch_bounds__(256) void k_lsm(const float* __restrict__ b2,
                                             float* __restrict__ out, int n) {
    int w = (blockIdx.x * blockDim.x + threadIdx.x) >> 5;
    int lane = threadIdx.x & 31;
    if (w >= n) return;
    float4 v = make_float4(0, 0, 0, 0);
    bool act = lane < 30;
    if (act) {
        if (lane < 10)
            v = ((const float4*)g_Fb)[(size_t)w * 30 + lane];
        else if (lane < 20)
            v = ((const float4*)g_Rb)[(size_t)w * 20 + (lane - 10)];
        else
            v = ((const float4*)g_Sb)[(size_t)w * 10 + (lane - 20)];
        float4 bb = ((const float4*)b2)[lane];
        v.x += bb.x; v.y += bb.y; v.z += bb.z; v.w += bb.w;
    }
    float m = act ? fmaxf(fmaxf(v.x, v.y), fmaxf(v.z, v.w)) : -INFINITY;
    #pragma unroll
    for (int o = 16; o > 0; o >>= 1) m = fmaxf(m, __shfl_xor_sync(0xffffffffu, m, o));
    float s = 0.0f;
    if (act) s = expf(v.x - m) + expf(v.y - m) + expf(v.z - m) + expf(v.w - m);
    #pragma unroll
    for (int o = 16; o > 0; o >>= 1) s += __shfl_xor_sync(0xffffffffu, s, o);
    float lse = m + logf(s);
    if (act) {
        float4 r = make_float4(v.x - lse, v.y - lse, v.z - lse, v.w - lse);
        ((float4*)out)[(size_t)w * 30 + lane] = r;
    }
}

// ---------------- launch ----------------
extern "C" void kernel_launch(void* const* d_in, const int* in_sizes, int n_in,
                              void* d_out, int out_size) {
    const float* x = (const float*)d_in[0];
    const void* ei = d_in[1];
    const float* W1_0 = (const float*)d_in[2];
    const float* W1_1 = (const float*)d_in[3];
    const float* W1_2 = (const float*)d_in[4];
    const float* b1 = (const float*)d_in[5];
    const float* W2_0 = (const float*)d_in[6];
    const float* W2_1 = (const float*)d_in[7];
    const float* W2_2 = (const float*)d_in[8];
    const float* b2 = (const float*)d_in[9];
    float* out = (float*)d_out;

    int n = in_sizes[0] / FIN;  // 50000
    int e = in_sizes[1] / 2;    // 800000

    cudaFuncSetAttribute(k_mma<1>, cudaFuncAttributeMaxDynamicSharedMemorySize, SMEMSZ);
    cudaFuncSetAttribute(k_mma<2>, cudaFuncAttributeMaxDynamicSharedMemorySize, SMEMSZ);

    // graph preprocessing
    k_zerodetect<<<(n + 255) / 256, 256>>>((const int2*)ei, n, e);
    k_convdeg<<<(e + 255) / 256, 256>>>(ei, e);
    k_dinv<<<(n + 255) / 256, 256>>>(n);
    k_scan1<<<NSB, SCB>>>(n);
    k_scan2<<<1, 32>>>();
    k_scan3<<<(n + 255) / 256, 256>>>(n, e);
    k_scatter<<<(e + 255) / 256, 256>>>(ei, e);

    // operand conversion
    k_xsplit<<<(n * FIN / 4 + 255) / 256, 256>>>(x, n * FIN / 4);
    k_wsplit<<<(384 * 256 + 120 * 384 + 255) / 256, 256>>>(W1_0, W1_1, W1_2, W2_0, W2_1, W2_2);

    int mt = (n + 127) / 128;
    int sb = (n + 7) / 8;

    // layer 1: [h0 | Gh] = x @ [W0|W1|W2]
    k_mma<1><<<dim3(3, mt), 256, SMEMSZ>>>(b1, n);
    k_spmmh<256, 0><<<sb, 256>>>(b1, n);  // U = P(G): h[:,128:256] + Uh
    k_spmmh<128, 1><<<sb, 256>>>(b1, n);  // V = P(Uh): h[:,256:384]

    // layer 2: F = h @ [W0|W1|W2]
    k_mma<2><<<dim3(1, mt), 256, SMEMSZ>>>(b1, n);
    k_spmmh<80, 2><<<sb, 256>>>(b1, n);   // R = P(Fh)
    k_spmmh<40, 3><<<sb, 256>>>(b1, n);   // S = P(Rh)

    k_lsm<<<(n + 7) / 8, 256>>>(b2, out, n);
}

// round 9
// speedup vs baseline: 2.2253x; 1.2935x over previous
#include <cuda_runtime.h>
#include <cuda_bf16.h>
#include <cuda_fp16.h>
#include <math.h>
#include <stdint.h>

#define NN 50000
#define EE 800000
#define FIN 256
#define HID 128
#define NCLS 40

#define SCB 512
#define NSB ((NN + SCB - 1) / SCB)  // 98

// ---------------- scratch (device globals; no allocation allowed) ----------------
__device__ int   g_is64;
__device__ int   g_dst[EE];
__device__ int   g_deg[NN];
__device__ float g_dinv[NN];
__device__ int   g_off[NN + 1];
__device__ int   g_cursor[NN];
__device__ int   g_bsum[NSB];
__device__ __align__(16) int2  g_csrw[EE];  // (src, dinv[src] bits)

// fp16 2-split operands: A = Ahi + Alo (exact); B uses hi only
__device__ __align__(16) __half g_xhi[(size_t)NN * FIN];
__device__ __align__(16) __half g_xlo[(size_t)NN * FIN];
__device__ __align__(16) __half g_w1t[384 * 256];   // [N=384][K=256]
__device__ __align__(16) __half g_w2t[120 * 384];   // [N=120][K=384]
__device__ __align__(16) __half g_hhi[(size_t)NN * 384];
__device__ __align__(16) __half g_hlo[(size_t)NN * 384];

// fp16 gather buffers for the SpMM chain
__device__ __align__(16) __half g_Gh[(size_t)NN * 256];  // x@[W1|W2]
__device__ __align__(16) __half g_Uh[(size_t)NN * 128];  // U[:,128:256]
__device__ __align__(16) __half g_Fh[(size_t)NN * 80];   // F[:,40:120]
__device__ __align__(16) __half g_Rh[(size_t)NN * 40];   // R[:,40:80]

__device__ __align__(16) float g_Fb[(size_t)NN * 120];   // fp32 for log_softmax
__device__ __align__(16) float g_Rb[(size_t)NN * 80];
__device__ __align__(16) float g_Sb[(size_t)NN * 40];

// ---------------- helpers ----------------
__device__ __forceinline__ uint32_t smem_u32(const void* p) {
    uint32_t a;
    asm("{ .reg .u64 t; cvta.to.shared.u64 t, %1; cvt.u32.u64 %0, t; }" : "=r"(a) : "l"(p));
    return a;
}

__device__ __forceinline__ void ldm_x4(uint32_t* r, uint32_t addr) {
    asm volatile("ldmatrix.sync.aligned.m8n8.x4.shared.b16 {%0,%1,%2,%3}, [%4];"
                 : "=r"(r[0]), "=r"(r[1]), "=r"(r[2]), "=r"(r[3]) : "r"(addr));
}

__device__ __forceinline__ void mma_f16(float* d, const uint32_t* a, uint32_t b0, uint32_t b1) {
    asm volatile(
        "mma.sync.aligned.m16n8k16.row.col.f32.f16.f16.f32 "
        "{%0,%1,%2,%3}, {%4,%5,%6,%7}, {%8,%9}, {%0,%1,%2,%3};"
        : "+f"(d[0]), "+f"(d[1]), "+f"(d[2]), "+f"(d[3])
        : "r"(a[0]), "r"(a[1]), "r"(a[2]), "r"(a[3]), "r"(b0), "r"(b1));
}

__device__ __forceinline__ void f16split(float a, __half& h, __half& l) {
    h = __float2half_rn(a);
    l = __float2half_rn(a - __half2float(h));
}

// ---------------- preprocessing ----------------
__global__ void k_zerodetect(const int2* __restrict__ ei2, int n, int e) {
    int i = blockIdx.x * blockDim.x + threadIdx.x;
    if (i < n) g_deg[i] = 0;
    if (blockIdx.x == 0) {
        __shared__ int nonzero;
        if (threadIdx.x == 0) nonzero = 0;
        __syncthreads();
        int t = threadIdx.x;
        if (t < 256 && t < e) {
            int2 p = ei2[t];
            if (p.y != 0) atomicAdd(&nonzero, 1);
        }
        __syncthreads();
        if (threadIdx.x == 0) g_is64 = (nonzero == 0) ? 1 : 0;
    }
}

__global__ void k_convdeg(const void* __restrict__ ei, int e) {
    int t = blockIdx.x * blockDim.x + threadIdx.x;
    if (t >= e) return;
    int d;
    if (g_is64) d = (int)((const long long*)ei)[(size_t)e + t];
    else        d = ((const int*)ei)[e + t];
    g_dst[t] = d;
    atomicAdd(&g_deg[d], 1);
}

__global__ void k_dinv(int n) {
    int i = blockIdx.x * blockDim.x + threadIdx.x;
    if (i < n) g_dinv[i] = rsqrtf((float)(g_deg[i] + 1));  // +1 self loop
}

// -------- hierarchical scan --------
__global__ __launch_bounds__(SCB) void k_scan1(int n) {
    __shared__ int wsum[SCB / 32];
    int tid = threadIdx.x, lane = tid & 31, wid = tid >> 5;
    int i = blockIdx.x * SCB + tid;
    int v = (i < n) ? g_deg[i] : 0;
    int inc = v;
    #pragma unroll
    for (int o = 1; o < 32; o <<= 1) {
        int t = __shfl_up_sync(0xffffffffu, inc, o);
        if (lane >= o) inc += t;
    }
    if (lane == 31) wsum[wid] = inc;
    __syncthreads();
    if (wid == 0) {
        int w = (lane < SCB / 32) ? wsum[lane] : 0;
        #pragma unroll
        for (int o = 1; o < SCB / 32; o <<= 1) {
            int t = __shfl_up_sync(0xffffffffu, w, o);
            if (lane >= o) w += t;
        }
        if (lane < SCB / 32) wsum[lane] = w;
    }
    __syncthreads();
    int ex = (inc - v) + (wid ? wsum[wid - 1] : 0);
    if (i < n) g_off[i] = ex;
    if (tid == SCB - 1) g_bsum[blockIdx.x] = ex + v;
}

__global__ void k_scan2() {
    int lane = threadIdx.x;
    int carry = 0;
    for (int b = 0; b < NSB; b += 32) {
        int idx = b + lane;
        int v = (idx < NSB) ? g_bsum[idx] : 0;
        int inc = v;
        #pragma unroll
        for (int o = 1; o < 32; o <<= 1) {
            int t = __shfl_up_sync(0xffffffffu, inc, o);
            if (lane >= o) inc += t;
        }
        int ex = carry + inc - v;
        if (idx < NSB) g_bsum[idx] = ex;
        carry += __shfl_sync(0xffffffffu, inc, 31);
    }
}

__global__ void k_scan3(int n, int e_total) {
    int i = blockIdx.x * blockDim.x + threadIdx.x;
    if (i < n) {
        int o = g_off[i] + g_bsum[i / SCB];
        g_off[i] = o;
        g_cursor[i] = o;
    }
    if (i == 0) g_off[n] = e_total;
}

__global__ void k_scatter(const void* __restrict__ ei, int e) {
    int t = blockIdx.x * blockDim.x + threadIdx.x;
    if (t >= e) return;
    int s;
    if (g_is64) s = (int)((const long long*)ei)[t];
    else        s = ((const int*)ei)[t];
    int d = g_dst[t];
    int p = atomicAdd(&g_cursor[d], 1);
    g_csrw[p] = make_int2(s, __float_as_int(g_dinv[s]));
}

// ---------------- data conversion ----------------
__global__ void k_xsplit(const float* __restrict__ x, int total4) {
    int i = blockIdx.x * blockDim.x + threadIdx.x;
    if (i >= total4) return;
    float4 v = ((const float4*)x)[i];
    __half h0, h1, h2, h3, l0, l1, l2, l3;
    f16split(v.x, h0, l0); f16split(v.y, h1, l1);
    f16split(v.z, h2, l2); f16split(v.w, h3, l3);
    ((__half2*)g_xhi)[i * 2] = __halves2half2(h0, h1);
    ((__half2*)g_xhi)[i * 2 + 1] = __halves2half2(h2, h3);
    ((__half2*)g_xlo)[i * 2] = __halves2half2(l0, l1);
    ((__half2*)g_xlo)[i * 2 + 1] = __halves2half2(l2, l3);
}

// merged W1T + W2T transpose (hi only — B error term dropped by design)
__global__ void k_wsplit(const float* __restrict__ w10, const float* __restrict__ w11,
                         const float* __restrict__ w12, const float* __restrict__ w20,
                         const float* __restrict__ w21, const float* __restrict__ w22) {
    int g = blockIdx.x * blockDim.x + threadIdx.x;
    if (g < 384 * 256) {
        int n = g / 256, k = g % 256;
        const float* w = (n < 128) ? w10 : (n < 256) ? w11 : w12;
        g_w1t[g] = __float2half_rn(w[k * 128 + (n & 127)]);
    } else if (g < 384 * 256 + 120 * 384) {
        int g2 = g - 384 * 256;
        int n = g2 / 384, k = g2 % 384;
        const float* w = (n < 40) ? w20 : (n < 80) ? w21 : w22;
        g_w2t[g2] = __float2half_rn(w[k * 40 + (n % 40)]);
    }
}

// ---------------- mma.sync GEMM (fp16 2-split: A·Bhi exact) ----------------
#define SPITCH 72
#define OFF_AH 0
#define OFF_AL (128 * SPITCH)
#define OFF_BH (2 * 128 * SPITCH)
#define SMEMSZ (3 * 128 * SPITCH * 2)  // 55296 bytes

__device__ __forceinline__ void ld_tile_sm(__half* dst, const __half* __restrict__ src,
                                           int row0, int validRows, int pitch, int k0, int tid) {
    #pragma unroll
    for (int it = 0; it < 4; it++) {
        int slot = tid + it * 256;
        int row = slot >> 3, q = slot & 7;
        float4 v = make_float4(0.f, 0.f, 0.f, 0.f);
        if (row < validRows)
            v = *reinterpret_cast<const float4*>(src + (size_t)(row0 + row) * pitch + k0 + q * 8);
        *reinterpret_cast<float4*>(dst + row * SPITCH + q * 8) = v;
    }
}

template <int LAYER>
__global__ __launch_bounds__(256) void k_mma(const float* __restrict__ b1, int M) {
    constexpr int K = (LAYER == 1) ? 256 : 384;
    constexpr int CH = K / 64;
    constexpr int APITCH = (LAYER == 1) ? 256 : 384;
    constexpr int BROWS = (LAYER == 1) ? 128 : 120;

    extern __shared__ __align__(16) __half sm[];
    uint32_t sbase = smem_u32(sm);

    int tid = threadIdx.x;
    int warp = tid >> 5, lane = tid & 31;
    int wm = warp & 3, wn = warp >> 2;
    int rowSel = lane & 15;
    int kSel = (lane >> 4) << 3;

    int bm = blockIdx.y * 128, bn = blockIdx.x * 128;
    int rowsA = M - bm; if (rowsA > 128) rowsA = 128;

    const __half* Ah = (LAYER == 1) ? g_xhi : g_hhi;
    const __half* Al = (LAYER == 1) ? g_xlo : g_hlo;
    const __half* Bh = (LAYER == 1) ? g_w1t : g_w2t;

    float acc[2][8][4];
    #pragma unroll
    for (int i = 0; i < 2; i++)
        #pragma unroll
        for (int j = 0; j < 8; j++)
            #pragma unroll
            for (int q = 0; q < 4; q++) acc[i][j][q] = 0.f;

    for (int c = 0; c < CH; c++) {
        int k0 = c * 64;
        ld_tile_sm(sm + OFF_AH, Ah, bm, rowsA, APITCH, k0, tid);
        ld_tile_sm(sm + OFF_AL, Al, bm, rowsA, APITCH, k0, tid);
        ld_tile_sm(sm + OFF_BH, Bh, bn, BROWS, K, k0, tid);
        __syncthreads();
        #pragma unroll
        for (int kb = 0; kb < 64; kb += 16) {
            uint32_t aH[2][4], aL[2][4];
            #pragma unroll
            for (int i = 0; i < 2; i++) {
                uint32_t rowA = wm * 32 + i * 16 + rowSel;
                ldm_x4(aH[i], sbase + 2u * (OFF_AH + rowA * SPITCH + kb + kSel));
                ldm_x4(aL[i], sbase + 2u * (OFF_AL + rowA * SPITCH + kb + kSel));
            }
            #pragma unroll
            for (int jj = 0; jj < 4; jj++) {
                uint32_t bH[4];
                uint32_t rowB = wn * 64 + jj * 16 + rowSel;
                ldm_x4(bH, sbase + 2u * (OFF_BH + rowB * SPITCH + kb + kSel));
                #pragma unroll
                for (int i = 0; i < 2; i++) {
                    mma_f16(acc[i][2 * jj], aH[i], bH[0], bH[2]);
                    mma_f16(acc[i][2 * jj], aL[i], bH[0], bH[2]);
                    mma_f16(acc[i][2 * jj + 1], aH[i], bH[1], bH[3]);
                    mma_f16(acc[i][2 * jj + 1], aL[i], bH[1], bH[3]);
                }
            }
        }
        __syncthreads();
    }

    int g = lane >> 2, tg = lane & 3;
    int m0 = bm + wm * 32;
    int nb = wn * 64;
    #pragma unroll
    for (int i = 0; i < 2; i++) {
        int r0 = m0 + i * 16 + g;
        int r1 = r0 + 8;
        #pragma unroll
        for (int j = 0; j < 8; j++) {
            int cl = nb + j * 8 + tg * 2;
            float2 v0 = make_float2(acc[i][j][0], acc[i][j][1]);
            float2 v1 = make_float2(acc[i][j][2], acc[i][j][3]);
            if (LAYER == 1) {
                if (blockIdx.x == 0) {
                    float2 bb = *(const float2*)&b1[cl];
                    if (r0 < M) {
                        float a0 = fmaxf(v0.x + bb.x, 0.f), a1 = fmaxf(v0.y + bb.y, 0.f);
                        __half h0, h1, l0, l1;
                        f16split(a0, h0, l0); f16split(a1, h1, l1);
                        *(__half2*)&g_hhi[(size_t)r0 * 384 + cl] = __halves2half2(h0, h1);
                        *(__half2*)&g_hlo[(size_t)r0 * 384 + cl] = __halves2half2(l0, l1);
                    }
                    if (r1 < M) {
                        float a0 = fmaxf(v1.x + bb.x, 0.f), a1 = fmaxf(v1.y + bb.y, 0.f);
                        __half h0, h1, l0, l1;
                        f16split(a0, h0, l0); f16split(a1, h1, l1);
                        *(__half2*)&g_hhi[(size_t)r1 * 384 + cl] = __halves2half2(h0, h1);
                        *(__half2*)&g_hlo[(size_t)r1 * 384 + cl] = __halves2half2(l0, l1);
                    }
                } else {
                    int cg = (blockIdx.x - 1) * 128 + cl;
                    if (r0 < M)
                        *(__half2*)&g_Gh[(size_t)r0 * 256 + cg] = __floats2half2_rn(v0.x, v0.y);
                    if (r1 < M)
                        *(__half2*)&g_Gh[(size_t)r1 * 256 + cg] = __floats2half2_rn(v1.x, v1.y);
                }
            } else {
                if (cl < 120) {
                    if (r0 < M) {
                        *(float2*)&g_Fb[(size_t)r0 * 120 + cl] = v0;
                        if (cl >= 40)
                            *(__half2*)&g_Fh[(size_t)r0 * 80 + (cl - 40)] = __floats2half2_rn(v0.x, v0.y);
                    }
                    if (r1 < M) {
                        *(float2*)&g_Fb[(size_t)r1 * 120 + cl] = v1;
                        if (cl >= 40)
                            *(__half2*)&g_Fh[(size_t)r1 * 80 + (cl - 40)] = __floats2half2_rn(v1.x, v1.y);
                    }
                }
            }
        }
    }
}

// ---------------- SpMM (fp16 gather, fp32 accumulate): one warp per row ----------------
template <int NH, int WHICH>
__global__ __launch_bounds__(256) void k_spmmh(const float* __restrict__ b1, int n) {
    constexpr int IT = (NH + 127) / 128;
    const __half* __restrict__ in =
        (WHICH == 0) ? g_Gh : (WHICH == 1) ? g_Uh : (WHICH == 2) ? g_Fh : g_Rh;

    int w = (blockIdx.x * blockDim.x + threadIdx.x) >> 5;
    int lane = threadIdx.x & 31;
    if (w >= n) return;
    float di = g_dinv[w];

    float4 acc[IT];
    #pragma unroll
    for (int t = 0; t < IT; t++) {
        int c = t * 128 + lane * 4;
        acc[t] = make_float4(0, 0, 0, 0);
        if (c < NH) {
            uint2 u = *(const uint2*)(in + (size_t)w * NH + c);
            float2 f0 = __half22float2(*(__half2*)&u.x);
            float2 f1 = __half22float2(*(__half2*)&u.y);
            acc[t] = make_float4(di * f0.x, di * f0.y, di * f1.x, di * f1.y);
        }
    }
    int jb = g_off[w], je = g_off[w + 1];
    int2 nxt = make_int2(0, 0);
    if (jb < je) nxt = g_csrw[jb];
    for (int j = jb; j < je; j++) {
        int2 cur = nxt;
        if (j + 1 < je) nxt = g_csrw[j + 1];
        int s = cur.x;
        float ws = __int_as_float(cur.y);
        #pragma unroll
        for (int t = 0; t < IT; t++) {
            int c = t * 128 + lane * 4;
            if (c < NH) {
                uint2 u = __ldg((const uint2*)(in + (size_t)s * NH + c));
                float2 f0 = __half22float2(*(__half2*)&u.x);
                float2 f1 = __half22float2(*(__half2*)&u.y);
                acc[t].x += ws * f0.x;
                acc[t].y += ws * f0.y;
                acc[t].z += ws * f1.x;
                acc[t].w += ws * f1.y;
            }
        }
    }
    #pragma unroll
    for (int t = 0; t < IT; t++) {
        int c = t * 128 + lane * 4;
        if (c >= NH) continue;
        float4 ov = make_float4(di * acc[t].x, di * acc[t].y, di * acc[t].z, di * acc[t].w);
        if (WHICH == 0) {
            if (c < 128) {
                int col = 128 + c;
                float4 bb = *(const float4*)&b1[col];
                float a0 = fmaxf(ov.x + bb.x, 0.f), a1 = fmaxf(ov.y + bb.y, 0.f);
                float a2 = fmaxf(ov.z + bb.z, 0.f), a3 = fmaxf(ov.w + bb.w, 0.f);
                __half h0, h1, h2, h3, l0, l1, l2, l3;
                f16split(a0, h0, l0); f16split(a1, h1, l1);
                f16split(a2, h2, l2); f16split(a3, h3, l3);
                *(__half2*)&g_hhi[(size_t)w * 384 + col] = __halves2half2(h0, h1);
                *(__half2*)&g_hhi[(size_t)w * 384 + col + 2] = __halves2half2(h2, h3);
                *(__half2*)&g_hlo[(size_t)w * 384 + col] = __halves2half2(l0, l1);
                *(__half2*)&g_hlo[(size_t)w * 384 + col + 2] = __halves2half2(l2, l3);
            } else {
                __half2 q0 = __floats2half2_rn(ov.x, ov.y);
                __half2 q1 = __floats2half2_rn(ov.z, ov.w);
                uint2 u;
                u.x = *(uint32_t*)&q0;
                u.y = *(uint32_t*)&q1;
                *(uint2*)&g_Uh[(size_t)w * 128 + (c - 128)] = u;
            }
        } else if (WHICH == 1) {
            int col = 256 + c;
            float4 bb = *(const float4*)&b1[col];
            float a0 = fmaxf(ov.x + bb.x, 0.f), a1 = fmaxf(ov.y + bb.y, 0.f);
            float a2 = fmaxf(ov.z + bb.z, 0.f), a3 = fmaxf(ov.w + bb.w, 0.f);
            __half h0, h1, h2, h3, l0, l1, l2, l3;
            f16split(a0, h0, l0); f16split(a1, h1, l1);
            f16split(a2, h2, l2); f16split(a3, h3, l3);
            *(__half2*)&g_hhi[(size_t)w * 384 + col] = __halves2half2(h0, h1);
            *(__half2*)&g_hhi[(size_t)w * 384 + col + 2] = __halves2half2(h2, h3);
            *(__half2*)&g_hlo[(size_t)w * 384 + col] = __halves2half2(l0, l1);
            *(__half2*)&g_hlo[(size_t)w * 384 + col + 2] = __halves2half2(l2, l3);
        } else if (WHICH == 2) {
            *(float4*)&g_Rb[(size_t)w * 80 + c] = ov;
            if (c >= 40) {
                __half2 q0 = __floats2half2_rn(ov.x, ov.y);
                __half2 q1 = __floats2half2_rn(ov.z, ov.w);
                uint2 u;
                u.x = *(uint32_t*)&q0;
                u.y = *(uint32_t*)&q1;
                *(uint2*)&g_Rh[(size_t)w * 40 + (c - 40)] = u;
            }
        } else {
            *(float4*)&g_Sb[(size_t)w * 40 + c] = ov;
        }
    }
}

// ---------------- final: gather blocks + b2, log_softmax over 120 ----------------
__global__ __launch_bounds__(256) void k_lsm(const float* __restrict__ b2,
                                             float* __restrict__ out, int n) {
    int w = (blockIdx.x * blockDim.x + threadIdx.x) >> 5;
    int lane = threadIdx.x & 31;
    if (w >= n) return;
    float4 v = make_float4(0, 0, 0, 0);
    bool act = lane < 30;
    if (act) {
        if (lane < 10)
            v = ((const float4*)g_Fb)[(size_t)w * 30 + lane];
        else if (lane < 20)
            v = ((const float4*)g_Rb)[(size_t)w * 20 + (lane - 10)];
        else
            v = ((const float4*)g_Sb)[(size_t)w * 10 + (lane - 20)];
        float4 bb = ((const float4*)b2)[lane];
        v.x += bb.x; v.y += bb.y; v.z += bb.z; v.w += bb.w;
    }
    float m = act ? fmaxf(fmaxf(v.x, v.y), fmaxf(v.z, v.w)) : -INFINITY;
    #pragma unroll
    for (int o = 16; o > 0; o >>= 1) m = fmaxf(m, __shfl_xor_sync(0xffffffffu, m, o));
    float s = 0.0f;
    if (act) s = expf(v.x - m) + expf(v.y - m) + expf(v.z - m) + expf(v.w - m);
    #pragma unroll
    for (int o = 16; o > 0; o >>= 1) s += __shfl_xor_sync(0xffffffffu, s, o);
    float lse = m + logf(s);
    if (act) {
        float4 r = make_float4(v.x - lse, v.y - lse, v.z - lse, v.w - lse);
        ((float4*)out)[(size_t)w * 30 + lane] = r;
    }
}

// ---------------- launch ----------------
extern "C" void kernel_launch(void* const* d_in, const int* in_sizes, int n_in,
                              void* d_out, int out_size) {
    const float* x = (const float*)d_in[0];
    const void* ei = d_in[1];
    const float* W1_0 = (const float*)d_in[2];
    const float* W1_1 = (const float*)d_in[3];
    const float* W1_2 = (const float*)d_in[4];
    const float* b1 = (const float*)d_in[5];
    const float* W2_0 = (const float*)d_in[6];
    const float* W2_1 = (const float*)d_in[7];
    const float* W2_2 = (const float*)d_in[8];
    const float* b2 = (const float*)d_in[9];
    float* out = (float*)d_out;

    int n = in_sizes[0] / FIN;  // 50000
    int e = in_sizes[1] / 2;    // 800000

    cudaFuncSetAttribute(k_mma<1>, cudaFuncAttributeMaxDynamicSharedMemorySize, SMEMSZ);
    cudaFuncSetAttribute(k_mma<2>, cudaFuncAttributeMaxDynamicSharedMemorySize, SMEMSZ);

    // graph preprocessing
    k_zerodetect<<<(n + 255) / 256, 256>>>((const int2*)ei, n, e);
    k_convdeg<<<(e + 255) / 256, 256>>>(ei, e);
    k_dinv<<<(n + 255) / 256, 256>>>(n);
    k_scan1<<<NSB, SCB>>>(n);
    k_scan2<<<1, 32>>>();
    k_scan3<<<(n + 255) / 256, 256>>>(n, e);
    k_scatter<<<(e + 255) / 256, 256>>>(ei, e);

    // operand conversion
    k_xsplit<<<(n * FIN / 4 + 255) / 256, 256>>>(x, n * FIN / 4);
    k_wsplit<<<(384 * 256 + 120 * 384 + 255) / 256, 256>>>(W1_0, W1_1, W1_2, W2_0, W2_1, W2_2);

    int mt = (n + 127) / 128;
    int sb = (n + 7) / 8;

    // layer 1: [h0 | Gh] = x @ [W0|W1|W2]
    k_mma<1><<<dim3(3, mt), 256, SMEMSZ>>>(b1, n);
    k_spmmh<256, 0><<<sb, 256>>>(b1, n);  // U = P(G): h[:,128:256] + Uh
    k_spmmh<128, 1><<<sb, 256>>>(b1, n);  // V = P(Uh): h[:,256:384]

    // layer 2: F = h @ [W0|W1|W2]
    k_mma<2><<<dim3(1, mt), 256, SMEMSZ>>>(b1, n);
    k_spmmh<80, 2><<<sb, 256>>>(b1, n);   // R = P(Fh)
    k_spmmh<40, 3><<<sb, 256>>>(b1, n);   // S = P(Rh)

    k_lsm<<<(n + 7) / 8, 256>>>(b2, out, n);
}

// round 10
// speedup vs baseline: 2.7462x; 1.2341x over previous
#include <cuda_runtime.h>
#include <cuda_fp16.h>
#include <math.h>
#include <stdint.h>

#define NN 50000
#define EE 800000
#define FIN 256
#define HID 128
#define NCLS 40

#define SCB 512
#define NSB ((NN + SCB - 1) / SCB)  // 98

// ---------------- scratch (device globals; no allocation allowed) ----------------
__device__ int   g_is64;
__device__ int   g_dst[EE];
__device__ int   g_deg[NN];
__device__ float g_dinv[NN];
__device__ int   g_off[NN + 1];
__device__ int   g_cursor[NN];
__device__ int   g_bsum[NSB];
__device__ __align__(16) int2  g_csrw[EE];  // (src, dinv[src] bits)

// fp16 operands
__device__ __align__(16) __half g_xh[(size_t)NN * FIN];
__device__ __align__(16) __half g_w1t[384 * 256];   // [N=384][K=256]
__device__ __align__(16) __half g_w2t[120 * 384];   // [N=120][K=384]
__device__ __align__(16) __half g_hh[(size_t)NN * 384];

// fp16 gather buffers for the SpMM chain
__device__ __align__(16) __half g_Gh[(size_t)NN * 256];  // x@[W1|W2]
__device__ __align__(16) __half g_Uh[(size_t)NN * 128];  // U[:,128:256]
__device__ __align__(16) __half g_Fh[(size_t)NN * 80];   // F[:,40:120]
__device__ __align__(16) __half g_Rh[(size_t)NN * 40];   // R[:,40:80]

__device__ __align__(16) float g_Fb[(size_t)NN * 120];   // fp32 for log_softmax
__device__ __align__(16) float g_Rb[(size_t)NN * 80];
__device__ __align__(16) float g_Sb[(size_t)NN * 40];

// ---------------- helpers ----------------
__device__ __forceinline__ uint32_t smem_u32(const void* p) {
    uint32_t a;
    asm("{ .reg .u64 t; cvta.to.shared.u64 t, %1; cvt.u32.u64 %0, t; }" : "=r"(a) : "l"(p));
    return a;
}

__device__ __forceinline__ void ldm_x4(uint32_t* r, uint32_t addr) {
    asm volatile("ldmatrix.sync.aligned.m8n8.x4.shared.b16 {%0,%1,%2,%3}, [%4];"
                 : "=r"(r[0]), "=r"(r[1]), "=r"(r[2]), "=r"(r[3]) : "r"(addr));
}

__device__ __forceinline__ void mma_f16(float* d, const uint32_t* a, uint32_t b0, uint32_t b1) {
    asm volatile(
        "mma.sync.aligned.m16n8k16.row.col.f32.f16.f16.f32 "
        "{%0,%1,%2,%3}, {%4,%5,%6,%7}, {%8,%9}, {%0,%1,%2,%3};"
        : "+f"(d[0]), "+f"(d[1]), "+f"(d[2]), "+f"(d[3])
        : "r"(a[0]), "r"(a[1]), "r"(a[2]), "r"(a[3]), "r"(b0), "r"(b1));
}

// ---------------- preprocessing ----------------
__global__ void k_zerodetect(const int2* __restrict__ ei2, int n, int e) {
    int i = blockIdx.x * blockDim.x + threadIdx.x;
    if (i < n) g_deg[i] = 0;
    if (blockIdx.x == 0) {
        __shared__ int nonzero;
        if (threadIdx.x == 0) nonzero = 0;
        __syncthreads();
        int t = threadIdx.x;
        if (t < 256 && t < e) {
            int2 p = ei2[t];
            if (p.y != 0) atomicAdd(&nonzero, 1);
        }
        __syncthreads();
        if (threadIdx.x == 0) g_is64 = (nonzero == 0) ? 1 : 0;
    }
}

__global__ void k_convdeg(const void* __restrict__ ei, int e) {
    int t = blockIdx.x * blockDim.x + threadIdx.x;
    if (t >= e) return;
    int d;
    if (g_is64) d = (int)((const long long*)ei)[(size_t)e + t];
    else        d = ((const int*)ei)[e + t];
    g_dst[t] = d;
    atomicAdd(&g_deg[d], 1);
}

__global__ void k_dinv(int n) {
    int i = blockIdx.x * blockDim.x + threadIdx.x;
    if (i < n) g_dinv[i] = rsqrtf((float)(g_deg[i] + 1));  // +1 self loop
}

// -------- hierarchical scan --------
__global__ __launch_bounds__(SCB) void k_scan1(int n) {
    __shared__ int wsum[SCB / 32];
    int tid = threadIdx.x, lane = tid & 31, wid = tid >> 5;
    int i = blockIdx.x * SCB + tid;
    int v = (i < n) ? g_deg[i] : 0;
    int inc = v;
    #pragma unroll
    for (int o = 1; o < 32; o <<= 1) {
        int t = __shfl_up_sync(0xffffffffu, inc, o);
        if (lane >= o) inc += t;
    }
    if (lane == 31) wsum[wid] = inc;
    __syncthreads();
    if (wid == 0) {
        int w = (lane < SCB / 32) ? wsum[lane] : 0;
        #pragma unroll
        for (int o = 1; o < SCB / 32; o <<= 1) {
            int t = __shfl_up_sync(0xffffffffu, w, o);
            if (lane >= o) w += t;
        }
        if (lane < SCB / 32) wsum[lane] = w;
    }
    __syncthreads();
    int ex = (inc - v) + (wid ? wsum[wid - 1] : 0);
    if (i < n) g_off[i] = ex;
    if (tid == SCB - 1) g_bsum[blockIdx.x] = ex + v;
}

__global__ void k_scan2() {
    int lane = threadIdx.x;
    int carry = 0;
    for (int b = 0; b < NSB; b += 32) {
        int idx = b + lane;
        int v = (idx < NSB) ? g_bsum[idx] : 0;
        int inc = v;
        #pragma unroll
        for (int o = 1; o < 32; o <<= 1) {
            int t = __shfl_up_sync(0xffffffffu, inc, o);
            if (lane >= o) inc += t;
        }
        int ex = carry + inc - v;
        if (idx < NSB) g_bsum[idx] = ex;
        carry += __shfl_sync(0xffffffffu, inc, 31);
    }
}

__global__ void k_scan3(int n, int e_total) {
    int i = blockIdx.x * blockDim.x + threadIdx.x;
    if (i < n) {
        int o = g_off[i] + g_bsum[i / SCB];
        g_off[i] = o;
        g_cursor[i] = o;
    }
    if (i == 0) g_off[n] = e_total;
}

__global__ void k_scatter(const void* __restrict__ ei, int e) {
    int t = blockIdx.x * blockDim.x + threadIdx.x;
    if (t >= e) return;
    int s;
    if (g_is64) s = (int)((const long long*)ei)[t];
    else        s = ((const int*)ei)[t];
    int d = g_dst[t];
    int p = atomicAdd(&g_cursor[d], 1);
    g_csrw[p] = make_int2(s, __float_as_int(g_dinv[s]));
}

// ---------------- data conversion ----------------
__global__ void k_xhalf(const float* __restrict__ x, int total4) {
    int i = blockIdx.x * blockDim.x + threadIdx.x;
    if (i >= total4) return;
    float4 v = ((const float4*)x)[i];
    ((__half2*)g_xh)[i * 2] = __floats2half2_rn(v.x, v.y);
    ((__half2*)g_xh)[i * 2 + 1] = __floats2half2_rn(v.z, v.w);
}

// merged W1T + W2T transpose to fp16
__global__ void k_wsplit(const float* __restrict__ w10, const float* __restrict__ w11,
                         const float* __restrict__ w12, const float* __restrict__ w20,
                         const float* __restrict__ w21, const float* __restrict__ w22) {
    int g = blockIdx.x * blockDim.x + threadIdx.x;
    if (g < 384 * 256) {
        int n = g / 256, k = g % 256;
        const float* w = (n < 128) ? w10 : (n < 256) ? w11 : w12;
        g_w1t[g] = __float2half_rn(w[k * 128 + (n & 127)]);
    } else if (g < 384 * 256 + 120 * 384) {
        int g2 = g - 384 * 256;
        int n = g2 / 384, k = g2 % 384;
        const float* w = (n < 40) ? w20 : (n < 80) ? w21 : w22;
        g_w2t[g2] = __float2half_rn(w[k * 40 + (n % 40)]);
    }
}

// ---------------- mma.sync GEMM (fp16) ----------------
#define SPITCH 72
#define OFF_A 0
#define OFF_B (128 * SPITCH)
#define SMEMSZ (2 * 128 * SPITCH * 2)  // 36864 bytes

__device__ __forceinline__ void ld_tile_sm(__half* dst, const __half* __restrict__ src,
                                           int row0, int validRows, int pitch, int k0, int tid) {
    #pragma unroll
    for (int it = 0; it < 4; it++) {
        int slot = tid + it * 256;
        int row = slot >> 3, q = slot & 7;
        float4 v = make_float4(0.f, 0.f, 0.f, 0.f);
        if (row < validRows)
            v = *reinterpret_cast<const float4*>(src + (size_t)(row0 + row) * pitch + k0 + q * 8);
        *reinterpret_cast<float4*>(dst + row * SPITCH + q * 8) = v;
    }
}

template <int LAYER>
__global__ __launch_bounds__(256) void k_mma(const float* __restrict__ b1, int M) {
    constexpr int K = (LAYER == 1) ? 256 : 384;
    constexpr int CH = K / 64;
    constexpr int APITCH = (LAYER == 1) ? 256 : 384;
    constexpr int BROWS = (LAYER == 1) ? 128 : 120;

    extern __shared__ __align__(16) __half sm[];
    uint32_t sbase = smem_u32(sm);

    int tid = threadIdx.x;
    int warp = tid >> 5, lane = tid & 31;
    int wm = warp & 3, wn = warp >> 2;
    int rowSel = lane & 15;
    int kSel = (lane >> 4) << 3;

    int bm = blockIdx.y * 128, bn = blockIdx.x * 128;
    int rowsA = M - bm; if (rowsA > 128) rowsA = 128;

    const __half* Ah = (LAYER == 1) ? g_xh : g_hh;
    const __half* Bh = (LAYER == 1) ? g_w1t : g_w2t;

    float acc[2][8][4];
    #pragma unroll
    for (int i = 0; i < 2; i++)
        #pragma unroll
        for (int j = 0; j < 8; j++)
            #pragma unroll
            for (int q = 0; q < 4; q++) acc[i][j][q] = 0.f;

    for (int c = 0; c < CH; c++) {
        int k0 = c * 64;
        ld_tile_sm(sm + OFF_A, Ah, bm, rowsA, APITCH, k0, tid);
        ld_tile_sm(sm + OFF_B, Bh, bn, BROWS, K, k0, tid);
        __syncthreads();
        #pragma unroll
        for (int kb = 0; kb < 64; kb += 16) {
            uint32_t aH[2][4];
            #pragma unroll
            for (int i = 0; i < 2; i++) {
                uint32_t rowA = wm * 32 + i * 16 + rowSel;
                ldm_x4(aH[i], sbase + 2u * (OFF_A + rowA * SPITCH + kb + kSel));
            }
            #pragma unroll
            for (int jj = 0; jj < 4; jj++) {
                uint32_t bH[4];
                uint32_t rowB = wn * 64 + jj * 16 + rowSel;
                ldm_x4(bH, sbase + 2u * (OFF_B + rowB * SPITCH + kb + kSel));
                #pragma unroll
                for (int i = 0; i < 2; i++) {
                    mma_f16(acc[i][2 * jj], aH[i], bH[0], bH[2]);
                    mma_f16(acc[i][2 * jj + 1], aH[i], bH[1], bH[3]);
                }
            }
        }
        __syncthreads();
    }

    int g = lane >> 2, tg = lane & 3;
    int m0 = bm + wm * 32;
    int nb = wn * 64;
    #pragma unroll
    for (int i = 0; i < 2; i++) {
        int r0 = m0 + i * 16 + g;
        int r1 = r0 + 8;
        #pragma unroll
        for (int j = 0; j < 8; j++) {
            int cl = nb + j * 8 + tg * 2;
            float2 v0 = make_float2(acc[i][j][0], acc[i][j][1]);
            float2 v1 = make_float2(acc[i][j][2], acc[i][j][3]);
            if (LAYER == 1) {
                if (blockIdx.x == 0) {
                    float2 bb = *(const float2*)&b1[cl];
                    if (r0 < M)
                        *(__half2*)&g_hh[(size_t)r0 * 384 + cl] = __floats2half2_rn(
                            fmaxf(v0.x + bb.x, 0.f), fmaxf(v0.y + bb.y, 0.f));
                    if (r1 < M)
                        *(__half2*)&g_hh[(size_t)r1 * 384 + cl] = __floats2half2_rn(
                            fmaxf(v1.x + bb.x, 0.f), fmaxf(v1.y + bb.y, 0.f));
                } else {
                    int cg = (blockIdx.x - 1) * 128 + cl;
                    if (r0 < M)
                        *(__half2*)&g_Gh[(size_t)r0 * 256 + cg] = __floats2half2_rn(v0.x, v0.y);
                    if (r1 < M)
                        *(__half2*)&g_Gh[(size_t)r1 * 256 + cg] = __floats2half2_rn(v1.x, v1.y);
                }
            } else {
                if (cl < 120) {
                    if (r0 < M) {
                        *(float2*)&g_Fb[(size_t)r0 * 120 + cl] = v0;
                        if (cl >= 40)
                            *(__half2*)&g_Fh[(size_t)r0 * 80 + (cl - 40)] = __floats2half2_rn(v0.x, v0.y);
                    }
                    if (r1 < M) {
                        *(float2*)&g_Fb[(size_t)r1 * 120 + cl] = v1;
                        if (cl >= 40)
                            *(__half2*)&g_Fh[(size_t)r1 * 80 + (cl - 40)] = __floats2half2_rn(v1.x, v1.y);
                    }
                }
            }
        }
    }
}

// ---------------- SpMM (fp16 gather, fp32 accumulate): one warp per row ----------------
// WHICH 0: g_Gh(256) -> h[:,128:256] (fp16 relu+b1) + g_Uh(128)
// WHICH 1: g_Uh(128) -> h[:,256:384] (fp16 relu+b1)
// WHICH 2: g_Fh(80)  -> g_Rb(80 fp32) + g_Rh(40)
// WHICH 3: g_Rh(40)  -> g_Sb(40 fp32)
template <int NH, int WHICH>
__global__ __launch_bounds__(256) void k_spmmh(const float* __restrict__ b1, int n) {
    constexpr int IT = (NH + 127) / 128;
    const __half* __restrict__ in =
        (WHICH == 0) ? g_Gh : (WHICH == 1) ? g_Uh : (WHICH == 2) ? g_Fh : g_Rh;

    int w = (blockIdx.x * blockDim.x + threadIdx.x) >> 5;
    int lane = threadIdx.x & 31;
    if (w >= n) return;
    float di = g_dinv[w];

    float4 acc[IT];
    #pragma unroll
    for (int t = 0; t < IT; t++) {
        int c = t * 128 + lane * 4;
        acc[t] = make_float4(0, 0, 0, 0);
        if (c < NH) {
            uint2 u = *(const uint2*)(in + (size_t)w * NH + c);
            float2 f0 = __half22float2(*(__half2*)&u.x);
            float2 f1 = __half22float2(*(__half2*)&u.y);
            acc[t] = make_float4(di * f0.x, di * f0.y, di * f1.x, di * f1.y);
        }
    }
    int jb = g_off[w], je = g_off[w + 1];
    int2 nxt = make_int2(0, 0);
    if (jb < je) nxt = g_csrw[jb];
    for (int j = jb; j < je; j++) {
        int2 cur = nxt;
        if (j + 1 < je) nxt = g_csrw[j + 1];
        int s = cur.x;
        float ws = __int_as_float(cur.y);
        #pragma unroll
        for (int t = 0; t < IT; t++) {
            int c = t * 128 + lane * 4;
            if (c < NH) {
                uint2 u = __ldg((const uint2*)(in + (size_t)s * NH + c));
                float2 f0 = __half22float2(*(__half2*)&u.x);
                float2 f1 = __half22float2(*(__half2*)&u.y);
                acc[t].x += ws * f0.x;
                acc[t].y += ws * f0.y;
                acc[t].z += ws * f1.x;
                acc[t].w += ws * f1.y;
            }
        }
    }
    #pragma unroll
    for (int t = 0; t < IT; t++) {
        int c = t * 128 + lane * 4;
        if (c >= NH) continue;
        float4 ov = make_float4(di * acc[t].x, di * acc[t].y, di * acc[t].z, di * acc[t].w);
        if (WHICH == 0) {
            if (c < 128) {
                int col = 128 + c;
                float4 bb = *(const float4*)&b1[col];
                __half2 q0 = __floats2half2_rn(fmaxf(ov.x + bb.x, 0.f), fmaxf(ov.y + bb.y, 0.f));
                __half2 q1 = __floats2half2_rn(fmaxf(ov.z + bb.z, 0.f), fmaxf(ov.w + bb.w, 0.f));
                *(__half2*)&g_hh[(size_t)w * 384 + col] = q0;
                *(__half2*)&g_hh[(size_t)w * 384 + col + 2] = q1;
            } else {
                __half2 q0 = __floats2half2_rn(ov.x, ov.y);
                __half2 q1 = __floats2half2_rn(ov.z, ov.w);
                uint2 u;
                u.x = *(uint32_t*)&q0;
                u.y = *(uint32_t*)&q1;
                *(uint2*)&g_Uh[(size_t)w * 128 + (c - 128)] = u;
            }
        } else if (WHICH == 1) {
            int col = 256 + c;
            float4 bb = *(const float4*)&b1[col];
            __half2 q0 = __floats2half2_rn(fmaxf(ov.x + bb.x, 0.f), fmaxf(ov.y + bb.y, 0.f));
            __half2 q1 = __floats2half2_rn(fmaxf(ov.z + bb.z, 0.f), fmaxf(ov.w + bb.w, 0.f));
            *(__half2*)&g_hh[(size_t)w * 384 + col] = q0;
            *(__half2*)&g_hh[(size_t)w * 384 + col + 2] = q1;
        } else if (WHICH == 2) {
            *(float4*)&g_Rb[(size_t)w * 80 + c] = ov;
            if (c >= 40) {
                __half2 q0 = __floats2half2_rn(ov.x, ov.y);
                __half2 q1 = __floats2half2_rn(ov.z, ov.w);
                uint2 u;
                u.x = *(uint32_t*)&q0;
                u.y = *(uint32_t*)&q1;
                *(uint2*)&g_Rh[(size_t)w * 40 + (c - 40)] = u;
            }
        } else {
            *(float4*)&g_Sb[(size_t)w * 40 + c] = ov;
        }
    }
}

// ---------------- final: gather blocks + b2, log_softmax over 120 ----------------
__global__ __launch_bounds__(256) void k_lsm(const float* __restrict__ b2,
                                             float* __restrict__ out, int n) {
    int w = (blockIdx.x * blockDim.x + threadIdx.x) >> 5;
    int lane = threadIdx.x & 31;
    if (w >= n) return;
    float4 v = make_float4(0, 0, 0, 0);
    bool act = lane < 30;
    if (act) {
        if (lane < 10)
            v = ((const float4*)g_Fb)[(size_t)w * 30 + lane];
        else if (lane < 20)
            v = ((const float4*)g_Rb)[(size_t)w * 20 + (lane - 10)];
        else
            v = ((const float4*)g_Sb)[(size_t)w * 10 + (lane - 20)];
        float4 bb = ((const float4*)b2)[lane];
        v.x += bb.x; v.y += bb.y; v.z += bb.z; v.w += bb.w;
    }
    float m = act ? fmaxf(fmaxf(v.x, v.y), fmaxf(v.z, v.w)) : -INFINITY;
    #pragma unroll
    for (int o = 16; o > 0; o >>= 1) m = fmaxf(m, __shfl_xor_sync(0xffffffffu, m, o));
    float s = 0.0f;
    if (act) s = expf(v.x - m) + expf(v.y - m) + expf(v.z - m) + expf(v.w - m);
    #pragma unroll
    for (int o = 16; o > 0; o >>= 1) s += __shfl_xor_sync(0xffffffffu, s, o);
    float lse = m + logf(s);
    if (act) {
        float4 r = make_float4(v.x - lse, v.y - lse, v.z - lse, v.w - lse);
        ((float4*)out)[(size_t)w * 30 + lane] = r;
    }
}

// ---------------- launch ----------------
extern "C" void kernel_launch(void* const* d_in, const int* in_sizes, int n_in,
                              void* d_out, int out_size) {
    const float* x = (const float*)d_in[0];
    const void* ei = d_in[1];
    const float* W1_0 = (const float*)d_in[2];
    const float* W1_1 = (const float*)d_in[3];
    const float* W1_2 = (const float*)d_in[4];
    const float* b1 = (const float*)d_in[5];
    const float* W2_0 = (const float*)d_in[6];
    const float* W2_1 = (const float*)d_in[7];
    const float* W2_2 = (const float*)d_in[8];
    const float* b2 = (const float*)d_in[9];
    float* out = (float*)d_out;

    int n = in_sizes[0] / FIN;  // 50000
    int e = in_sizes[1] / 2;    // 800000

    cudaFuncSetAttribute(k_mma<1>, cudaFuncAttributeMaxDynamicSharedMemorySize, SMEMSZ);
    cudaFuncSetAttribute(k_mma<2>, cudaFuncAttributeMaxDynamicSharedMemorySize, SMEMSZ);

    // graph preprocessing
    k_zerodetect<<<(n + 255) / 256, 256>>>((const int2*)ei, n, e);
    k_convdeg<<<(e + 255) / 256, 256>>>(ei, e);
    k_dinv<<<(n + 255) / 256, 256>>>(n);
    k_scan1<<<NSB, SCB>>>(n);
    k_scan2<<<1, 32>>>();
    k_scan3<<<(n + 255) / 256, 256>>>(n, e);
    k_scatter<<<(e + 255) / 256, 256>>>(ei, e);

    // operand conversion
    k_xhalf<<<(n * FIN / 4 + 255) / 256, 256>>>(x, n * FIN / 4);
    k_wsplit<<<(384 * 256 + 120 * 384 + 255) / 256, 256>>>(W1_0, W1_1, W1_2, W2_0, W2_1, W2_2);

    int mt = (n + 127) / 128;
    int sb = (n + 7) / 8;

    // layer 1: [h0 | Gh] = x @ [W0|W1|W2]
    k_mma<1><<<dim3(3, mt), 256, SMEMSZ>>>(b1, n);
    k_spmmh<256, 0><<<sb, 256>>>(b1, n);  // U = P(G): h[:,128:256] + Uh
    k_spmmh<128, 1><<<sb, 256>>>(b1, n);  // V = P(Uh): h[:,256:384]

    // layer 2: F = h @ [W0|W1|W2]
    k_mma<2><<<dim3(1, mt), 256, SMEMSZ>>>(b1, n);
    k_spmmh<80, 2><<<sb, 256>>>(b1, n);   // R = P(Fh)
    k_spmmh<40, 3><<<sb, 256>>>(b1, n);   // S = P(Rh)

    k_lsm<<<(n + 7) / 8, 256>>>(b2, out, n);
}

// round 11
// speedup vs baseline: 2.8902x; 1.0524x over previous
#include <cuda_runtime.h>
#include <cuda_fp16.h>
#include <math.h>
#include <stdint.h>

#define NN 50000
#define EE 800000
#define FIN 256
#define HID 128
#define NCLS 40

#define SCB 512
#define NSB ((NN + SCB - 1) / SCB)  // 98

// ---------------- scratch (device globals; no allocation allowed) ----------------
__device__ int   g_is64;
__device__ int   g_dst[EE];
__device__ int   g_deg[NN];
__device__ float g_dinv[NN];
__device__ int   g_off[NN + 1];
__device__ int   g_cursor[NN];
__device__ int   g_bsum[NSB];
__device__ __align__(16) int2  g_csrw[EE];  // (src, dinv[src] bits)

// fp16 operands
__device__ __align__(16) __half g_xh[(size_t)NN * FIN];
__device__ __align__(16) __half g_w1t[384 * 256];   // [N=384][K=256]
__device__ __align__(16) __half g_w2t[120 * 384];   // [N=120][K=384]
__device__ __align__(16) __half g_hh[(size_t)NN * 384];

// fp16 gather buffers for the SpMM chain
__device__ __align__(16) __half g_Gh[(size_t)NN * 256];  // x@[W1|W2]
__device__ __align__(16) __half g_Uh[(size_t)NN * 128];  // U[:,128:256]
__device__ __align__(16) __half g_Fh[(size_t)NN * 80];   // F[:,40:120]
__device__ __align__(16) __half g_Rh[(size_t)NN * 40];   // R[:,40:80]

__device__ __align__(16) float g_Fb[(size_t)NN * 120];   // fp32 for log_softmax
__device__ __align__(16) float g_Rb[(size_t)NN * 80];
__device__ __align__(16) float g_Sb[(size_t)NN * 40];

// ---------------- helpers ----------------
__device__ __forceinline__ uint32_t smem_u32(const void* p) {
    uint32_t a;
    asm("{ .reg .u64 t; cvta.to.shared.u64 t, %1; cvt.u32.u64 %0, t; }" : "=r"(a) : "l"(p));
    return a;
}

__device__ __forceinline__ void ldm_x4(uint32_t* r, uint32_t addr) {
    asm volatile("ldmatrix.sync.aligned.m8n8.x4.shared.b16 {%0,%1,%2,%3}, [%4];"
                 : "=r"(r[0]), "=r"(r[1]), "=r"(r[2]), "=r"(r[3]) : "r"(addr));
}

__device__ __forceinline__ void mma_f16(float* d, const uint32_t* a, uint32_t b0, uint32_t b1) {
    asm volatile(
        "mma.sync.aligned.m16n8k16.row.col.f32.f16.f16.f32 "
        "{%0,%1,%2,%3}, {%4,%5,%6,%7}, {%8,%9}, {%0,%1,%2,%3};"
        : "+f"(d[0]), "+f"(d[1]), "+f"(d[2]), "+f"(d[3])
        : "r"(a[0]), "r"(a[1]), "r"(a[2]), "r"(a[3]), "r"(b0), "r"(b1));
}

// ---------------- preprocessing ----------------
__global__ void k_zerodetect(const int2* __restrict__ ei2, int n, int e) {
    int i = blockIdx.x * blockDim.x + threadIdx.x;
    if (i < n) g_deg[i] = 0;
    if (blockIdx.x == 0) {
        __shared__ int nonzero;
        if (threadIdx.x == 0) nonzero = 0;
        __syncthreads();
        int t = threadIdx.x;
        if (t < 256 && t < e) {
            int2 p = ei2[t];
            if (p.y != 0) atomicAdd(&nonzero, 1);
        }
        __syncthreads();
        if (threadIdx.x == 0) g_is64 = (nonzero == 0) ? 1 : 0;
    }
}

__global__ void k_convdeg(const void* __restrict__ ei, int e) {
    int t = blockIdx.x * blockDim.x + threadIdx.x;
    if (t >= e) return;
    int d;
    if (g_is64) d = (int)((const long long*)ei)[(size_t)e + t];
    else        d = ((const int*)ei)[e + t];
    g_dst[t] = d;
    atomicAdd(&g_deg[d], 1);
}

__global__ void k_dinv(int n) {
    int i = blockIdx.x * blockDim.x + threadIdx.x;
    if (i < n) g_dinv[i] = rsqrtf((float)(g_deg[i] + 1));  // +1 self loop
}

// -------- hierarchical scan --------
__global__ __launch_bounds__(SCB) void k_scan1(int n) {
    __shared__ int wsum[SCB / 32];
    int tid = threadIdx.x, lane = tid & 31, wid = tid >> 5;
    int i = blockIdx.x * SCB + tid;
    int v = (i < n) ? g_deg[i] : 0;
    int inc = v;
    #pragma unroll
    for (int o = 1; o < 32; o <<= 1) {
        int t = __shfl_up_sync(0xffffffffu, inc, o);
        if (lane >= o) inc += t;
    }
    if (lane == 31) wsum[wid] = inc;
    __syncthreads();
    if (wid == 0) {
        int w = (lane < SCB / 32) ? wsum[lane] : 0;
        #pragma unroll
        for (int o = 1; o < SCB / 32; o <<= 1) {
            int t = __shfl_up_sync(0xffffffffu, w, o);
            if (lane >= o) w += t;
        }
        if (lane < SCB / 32) wsum[lane] = w;
    }
    __syncthreads();
    int ex = (inc - v) + (wid ? wsum[wid - 1] : 0);
    if (i < n) g_off[i] = ex;
    if (tid == SCB - 1) g_bsum[blockIdx.x] = ex + v;
}

__global__ void k_scan2() {
    int lane = threadIdx.x;
    int carry = 0;
    for (int b = 0; b < NSB; b += 32) {
        int idx = b + lane;
        int v = (idx < NSB) ? g_bsum[idx] : 0;
        int inc = v;
        #pragma unroll
        for (int o = 1; o < 32; o <<= 1) {
            int t = __shfl_up_sync(0xffffffffu, inc, o);
            if (lane >= o) inc += t;
        }
        int ex = carry + inc - v;
        if (idx < NSB) g_bsum[idx] = ex;
        carry += __shfl_sync(0xffffffffu, inc, 31);
    }
}

__global__ void k_scan3(int n, int e_total) {
    int i = blockIdx.x * blockDim.x + threadIdx.x;
    if (i < n) {
        int o = g_off[i] + g_bsum[i / SCB];
        g_off[i] = o;
        g_cursor[i] = o;
    }
    if (i == 0) g_off[n] = e_total;
}

__global__ void k_scatter(const void* __restrict__ ei, int e) {
    int t = blockIdx.x * blockDim.x + threadIdx.x;
    if (t >= e) return;
    int s;
    if (g_is64) s = (int)((const long long*)ei)[t];
    else        s = ((const int*)ei)[t];
    int d = g_dst[t];
    int p = atomicAdd(&g_cursor[d], 1);
    g_csrw[p] = make_int2(s, __float_as_int(g_dinv[s]));
}

// ---------------- data conversion ----------------
__global__ void k_xhalf(const float* __restrict__ x, int total4) {
    int i = blockIdx.x * blockDim.x + threadIdx.x;
    if (i >= total4) return;
    float4 v = ((const float4*)x)[i];
    ((__half2*)g_xh)[i * 2] = __floats2half2_rn(v.x, v.y);
    ((__half2*)g_xh)[i * 2 + 1] = __floats2half2_rn(v.z, v.w);
}

// merged W1T + W2T transpose to fp16
__global__ void k_wsplit(const float* __restrict__ w10, const float* __restrict__ w11,
                         const float* __restrict__ w12, const float* __restrict__ w20,
                         const float* __restrict__ w21, const float* __restrict__ w22) {
    int g = blockIdx.x * blockDim.x + threadIdx.x;
    if (g < 384 * 256) {
        int n = g / 256, k = g % 256;
        const float* w = (n < 128) ? w10 : (n < 256) ? w11 : w12;
        g_w1t[g] = __float2half_rn(w[k * 128 + (n & 127)]);
    } else if (g < 384 * 256 + 120 * 384) {
        int g2 = g - 384 * 256;
        int n = g2 / 384, k = g2 % 384;
        const float* w = (n < 40) ? w20 : (n < 80) ? w21 : w22;
        g_w2t[g2] = __float2half_rn(w[k * 40 + (n % 40)]);
    }
}

// ---------------- mma.sync GEMM (fp16) ----------------
#define SPITCH 72
#define OFF_A 0
#define OFF_B (128 * SPITCH)
#define SMEMSZ (2 * 128 * SPITCH * 2)  // 36864 bytes

__device__ __forceinline__ void ld_tile_sm(__half* dst, const __half* __restrict__ src,
                                           int row0, int validRows, int pitch, int k0, int tid) {
    #pragma unroll
    for (int it = 0; it < 4; it++) {
        int slot = tid + it * 256;
        int row = slot >> 3, q = slot & 7;
        float4 v = make_float4(0.f, 0.f, 0.f, 0.f);
        if (row < validRows)
            v = *reinterpret_cast<const float4*>(src + (size_t)(row0 + row) * pitch + k0 + q * 8);
        *reinterpret_cast<float4*>(dst + row * SPITCH + q * 8) = v;
    }
}

template <int LAYER>
__global__ __launch_bounds__(256) void k_mma(const float* __restrict__ b1, int M) {
    constexpr int K = (LAYER == 1) ? 256 : 384;
    constexpr int CH = K / 64;
    constexpr int APITCH = (LAYER == 1) ? 256 : 384;
    constexpr int BROWS = (LAYER == 1) ? 128 : 120;

    extern __shared__ __align__(16) __half sm[];
    uint32_t sbase = smem_u32(sm);

    int tid = threadIdx.x;
    int warp = tid >> 5, lane = tid & 31;
    int wm = warp & 3, wn = warp >> 2;
    int rowSel = lane & 15;
    int kSel = (lane >> 4) << 3;

    int bm = blockIdx.y * 128, bn = blockIdx.x * 128;
    int rowsA = M - bm; if (rowsA > 128) rowsA = 128;

    const __half* Ah = (LAYER == 1) ? g_xh : g_hh;
    const __half* Bh = (LAYER == 1) ? g_w1t : g_w2t;

    float acc[2][8][4];
    #pragma unroll
    for (int i = 0; i < 2; i++)
        #pragma unroll
        for (int j = 0; j < 8; j++)
            #pragma unroll
            for (int q = 0; q < 4; q++) acc[i][j][q] = 0.f;

    for (int c = 0; c < CH; c++) {
        int k0 = c * 64;
        ld_tile_sm(sm + OFF_A, Ah, bm, rowsA, APITCH, k0, tid);
        ld_tile_sm(sm + OFF_B, Bh, bn, BROWS, K, k0, tid);
        __syncthreads();
        #pragma unroll
        for (int kb = 0; kb < 64; kb += 16) {
            uint32_t aH[2][4];
            #pragma unroll
            for (int i = 0; i < 2; i++) {
                uint32_t rowA = wm * 32 + i * 16 + rowSel;
                ldm_x4(aH[i], sbase + 2u * (OFF_A + rowA * SPITCH + kb + kSel));
            }
            #pragma unroll
            for (int jj = 0; jj < 4; jj++) {
                uint32_t bH[4];
                uint32_t rowB = wn * 64 + jj * 16 + rowSel;
                ldm_x4(bH, sbase + 2u * (OFF_B + rowB * SPITCH + kb + kSel));
                #pragma unroll
                for (int i = 0; i < 2; i++) {
                    mma_f16(acc[i][2 * jj], aH[i], bH[0], bH[2]);
                    mma_f16(acc[i][2 * jj + 1], aH[i], bH[1], bH[3]);
                }
            }
        }
        __syncthreads();
    }

    int g = lane >> 2, tg = lane & 3;
    int m0 = bm + wm * 32;
    int nb = wn * 64;
    #pragma unroll
    for (int i = 0; i < 2; i++) {
        int r0 = m0 + i * 16 + g;
        int r1 = r0 + 8;
        #pragma unroll
        for (int j = 0; j < 8; j++) {
            int cl = nb + j * 8 + tg * 2;
            float2 v0 = make_float2(acc[i][j][0], acc[i][j][1]);
            float2 v1 = make_float2(acc[i][j][2], acc[i][j][3]);
            if (LAYER == 1) {
                if (blockIdx.x == 0) {
                    float2 bb = *(const float2*)&b1[cl];
                    if (r0 < M)
                        *(__half2*)&g_hh[(size_t)r0 * 384 + cl] = __floats2half2_rn(
                            fmaxf(v0.x + bb.x, 0.f), fmaxf(v0.y + bb.y, 0.f));
                    if (r1 < M)
                        *(__half2*)&g_hh[(size_t)r1 * 384 + cl] = __floats2half2_rn(
                            fmaxf(v1.x + bb.x, 0.f), fmaxf(v1.y + bb.y, 0.f));
                } else {
                    int cg = (blockIdx.x - 1) * 128 + cl;
                    if (r0 < M)
                        *(__half2*)&g_Gh[(size_t)r0 * 256 + cg] = __floats2half2_rn(v0.x, v0.y);
                    if (r1 < M)
                        *(__half2*)&g_Gh[(size_t)r1 * 256 + cg] = __floats2half2_rn(v1.x, v1.y);
                }
            } else {
                if (cl < 120) {
                    if (r0 < M) {
                        *(float2*)&g_Fb[(size_t)r0 * 120 + cl] = v0;
                        if (cl >= 40)
                            *(__half2*)&g_Fh[(size_t)r0 * 80 + (cl - 40)] = __floats2half2_rn(v0.x, v0.y);
                    }
                    if (r1 < M) {
                        *(float2*)&g_Fb[(size_t)r1 * 120 + cl] = v1;
                        if (cl >= 40)
                            *(__half2*)&g_Fh[(size_t)r1 * 80 + (cl - 40)] = __floats2half2_rn(v1.x, v1.y);
                    }
                }
            }
        }
    }
}

// ---------------- SpMM (fp16 gather, fp32 accumulate): one warp per row ----------------
template <int NH, int WHICH>
__global__ __launch_bounds__(256) void k_spmmh(const float* __restrict__ b1, int n) {
    constexpr int IT = (NH + 127) / 128;
    const __half* __restrict__ in =
        (WHICH == 0) ? g_Gh : (WHICH == 1) ? g_Uh : (WHICH == 2) ? g_Fh : g_Rh;

    int w = (blockIdx.x * blockDim.x + threadIdx.x) >> 5;
    int lane = threadIdx.x & 31;
    if (w >= n) return;
    float di = g_dinv[w];

    float4 acc[IT];
    #pragma unroll
    for (int t = 0; t < IT; t++) {
        int c = t * 128 + lane * 4;
        acc[t] = make_float4(0, 0, 0, 0);
        if (c < NH) {
            uint2 u = *(const uint2*)(in + (size_t)w * NH + c);
            float2 f0 = __half22float2(*(__half2*)&u.x);
            float2 f1 = __half22float2(*(__half2*)&u.y);
            acc[t] = make_float4(di * f0.x, di * f0.y, di * f1.x, di * f1.y);
        }
    }
    int jb = g_off[w], je = g_off[w + 1];
    int2 nxt = make_int2(0, 0);
    if (jb < je) nxt = g_csrw[jb];
    for (int j = jb; j < je; j++) {
        int2 cur = nxt;
        if (j + 1 < je) nxt = g_csrw[j + 1];
        int s = cur.x;
        float ws = __int_as_float(cur.y);
        #pragma unroll
        for (int t = 0; t < IT; t++) {
            int c = t * 128 + lane * 4;
            if (c < NH) {
                uint2 u = __ldg((const uint2*)(in + (size_t)s * NH + c));
                float2 f0 = __half22float2(*(__half2*)&u.x);
                float2 f1 = __half22float2(*(__half2*)&u.y);
                acc[t].x += ws * f0.x;
                acc[t].y += ws * f0.y;
                acc[t].z += ws * f1.x;
                acc[t].w += ws * f1.y;
            }
        }
    }
    #pragma unroll
    for (int t = 0; t < IT; t++) {
        int c = t * 128 + lane * 4;
        if (c >= NH) continue;
        float4 ov = make_float4(di * acc[t].x, di * acc[t].y, di * acc[t].z, di * acc[t].w);
        if (WHICH == 0) {
            if (c < 128) {
                int col = 128 + c;
                float4 bb = *(const float4*)&b1[col];
                __half2 q0 = __floats2half2_rn(fmaxf(ov.x + bb.x, 0.f), fmaxf(ov.y + bb.y, 0.f));
                __half2 q1 = __floats2half2_rn(fmaxf(ov.z + bb.z, 0.f), fmaxf(ov.w + bb.w, 0.f));
                *(__half2*)&g_hh[(size_t)w * 384 + col] = q0;
                *(__half2*)&g_hh[(size_t)w * 384 + col + 2] = q1;
            } else {
                __half2 q0 = __floats2half2_rn(ov.x, ov.y);
                __half2 q1 = __floats2half2_rn(ov.z, ov.w);
                uint2 u;
                u.x = *(uint32_t*)&q0;
                u.y = *(uint32_t*)&q1;
                *(uint2*)&g_Uh[(size_t)w * 128 + (c - 128)] = u;
            }
        } else if (WHICH == 1) {
            int col = 256 + c;
            float4 bb = *(const float4*)&b1[col];
            __half2 q0 = __floats2half2_rn(fmaxf(ov.x + bb.x, 0.f), fmaxf(ov.y + bb.y, 0.f));
            __half2 q1 = __floats2half2_rn(fmaxf(ov.z + bb.z, 0.f), fmaxf(ov.w + bb.w, 0.f));
            *(__half2*)&g_hh[(size_t)w * 384 + col] = q0;
            *(__half2*)&g_hh[(size_t)w * 384 + col + 2] = q1;
        } else if (WHICH == 2) {
            *(float4*)&g_Rb[(size_t)w * 80 + c] = ov;
            if (c >= 40) {
                __half2 q0 = __floats2half2_rn(ov.x, ov.y);
                __half2 q1 = __floats2half2_rn(ov.z, ov.w);
                uint2 u;
                u.x = *(uint32_t*)&q0;
                u.y = *(uint32_t*)&q1;
                *(uint2*)&g_Rh[(size_t)w * 40 + (c - 40)] = u;
            }
        } else {
            *(float4*)&g_Sb[(size_t)w * 40 + c] = ov;
        }
    }
}

// ---------------- final: gather blocks + b2, log_softmax over 120 ----------------
__global__ __launch_bounds__(256) void k_lsm(const float* __restrict__ b2,
                                             float* __restrict__ out, int n) {
    int w = (blockIdx.x * blockDim.x + threadIdx.x) >> 5;
    int lane = threadIdx.x & 31;
    if (w >= n) return;
    float4 v = make_float4(0, 0, 0, 0);
    bool act = lane < 30;
    if (act) {
        if (lane < 10)
            v = ((const float4*)g_Fb)[(size_t)w * 30 + lane];
        else if (lane < 20)
            v = ((const float4*)g_Rb)[(size_t)w * 20 + (lane - 10)];
        else
            v = ((const float4*)g_Sb)[(size_t)w * 10 + (lane - 20)];
        float4 bb = ((const float4*)b2)[lane];
        v.x += bb.x; v.y += bb.y; v.z += bb.z; v.w += bb.w;
    }
    float m = act ? fmaxf(fmaxf(v.x, v.y), fmaxf(v.z, v.w)) : -INFINITY;
    #pragma unroll
    for (int o = 16; o > 0; o >>= 1) m = fmaxf(m, __shfl_xor_sync(0xffffffffu, m, o));
    float s = 0.0f;
    if (act) s = expf(v.x - m) + expf(v.y - m) + expf(v.z - m) + expf(v.w - m);
    #pragma unroll
    for (int o = 16; o > 0; o >>= 1) s += __shfl_xor_sync(0xffffffffu, s, o);
    float lse = m + logf(s);
    if (act) {
        float4 r = make_float4(v.x - lse, v.y - lse, v.z - lse, v.w - lse);
        ((float4*)out)[(size_t)w * 30 + lane] = r;
    }
}

// ---------------- launch ----------------
extern "C" void kernel_launch(void* const* d_in, const int* in_sizes, int n_in,
                              void* d_out, int out_size) {
    const float* x = (const float*)d_in[0];
    const void* ei = d_in[1];
    const float* W1_0 = (const float*)d_in[2];
    const float* W1_1 = (const float*)d_in[3];
    const float* W1_2 = (const float*)d_in[4];
    const float* b1 = (const float*)d_in[5];
    const float* W2_0 = (const float*)d_in[6];
    const float* W2_1 = (const float*)d_in[7];
    const float* W2_2 = (const float*)d_in[8];
    const float* b2 = (const float*)d_in[9];
    float* out = (float*)d_out;

    int n = in_sizes[0] / FIN;  // 50000
    int e = in_sizes[1] / 2;    // 800000

    static cudaStream_t s2 = nullptr;
    static cudaEvent_t evFork = nullptr, evJoin = nullptr;
    if (s2 == nullptr) {
        cudaStreamCreateWithFlags(&s2, cudaStreamNonBlocking);
        cudaEventCreateWithFlags(&evFork, cudaEventDisableTiming);
        cudaEventCreateWithFlags(&evJoin, cudaEventDisableTiming);
        cudaFuncSetAttribute(k_mma<1>, cudaFuncAttributeMaxDynamicSharedMemorySize, SMEMSZ);
        cudaFuncSetAttribute(k_mma<2>, cudaFuncAttributeMaxDynamicSharedMemorySize, SMEMSZ);
    }

    // ---- fork: graph preprocessing runs on s2, parallel to conversion+mma1 ----
    cudaEventRecord(evFork, 0);
    cudaStreamWaitEvent(s2, evFork, 0);

    k_zerodetect<<<(n + 255) / 256, 256, 0, s2>>>((const int2*)ei, n, e);
    k_convdeg<<<(e + 255) / 256, 256, 0, s2>>>(ei, e);
    k_dinv<<<(n + 255) / 256, 256, 0, s2>>>(n);
    k_scan1<<<NSB, SCB, 0, s2>>>(n);
    k_scan2<<<1, 32, 0, s2>>>();
    k_scan3<<<(n + 255) / 256, 256, 0, s2>>>(n, e);
    k_scatter<<<(e + 255) / 256, 256, 0, s2>>>(ei, e);
    cudaEventRecord(evJoin, s2);

    // ---- main branch: operand conversion + layer-1 GEMM ----
    k_xhalf<<<(n * FIN / 4 + 255) / 256, 256>>>(x, n * FIN / 4);
    k_wsplit<<<(384 * 256 + 120 * 384 + 255) / 256, 256>>>(W1_0, W1_1, W1_2, W2_0, W2_1, W2_2);

    int mt = (n + 127) / 128;
    int sb = (n + 7) / 8;

    k_mma<1><<<dim3(3, mt), 256, SMEMSZ>>>(b1, n);  // [h0 | Gh] = x @ [W0|W1|W2]

    // ---- join: SpMM chain needs the CSR ----
    cudaStreamWaitEvent(0, evJoin, 0);

    k_spmmh<256, 0><<<sb, 256>>>(b1, n);  // U = P(G): h[:,128:256] + Uh
    k_spmmh<128, 1><<<sb, 256>>>(b1, n);  // V = P(Uh): h[:,256:384]

    k_mma<2><<<dim3(1, mt), 256, SMEMSZ>>>(b1, n);  // F = h @ [W0|W1|W2]
    k_spmmh<80, 2><<<sb, 256>>>(b1, n);   // R = P(Fh)
    k_spmmh<40, 3><<<sb, 256>>>(b1, n);   // S = P(Rh)

    k_lsm<<<(n + 7) / 8, 256>>>(b2, out, n);
}